// round 13
// baseline (speedup 1.0000x reference)
#include <cuda_runtime.h>
#include <cuda_fp16.h>
#include <math.h>

#define BATCH 8
#define SEQ   512
#define CDIM  2048
#define NH    16
#define HD    128
#define MTOK  (BATCH*SEQ)      // 4096
#define F3    (3*CDIM)         // 6144

// Scratch (static device arrays; no allocation anywhere)
__device__ __half g_q [BATCH*NH*SEQ*HD];    // [bh][t][d] scaled fp16 (rope'd)
__device__ __half g_k [BATCH*NH*SEQ*HD];    // [bh][t][d] fp16 (rope'd)
__device__ __half g_vT[BATCH*NH*HD*SEQ];    // [bh][d][t] fp16 (transposed)
__device__ __half g_y [MTOK * CDIM];        // [b,t,C] fp16
__device__ __half g_xh[MTOK * CDIM];        // fp16 x
__device__ __half g_w1[F3 * CDIM];          // fp16 Wqkv
__device__ __half g_w2[CDIM * CDIM];        // fp16 Wout

// ---------------------------------------------------------------------------
__device__ __forceinline__ unsigned smem_u32(const void* p) {
    unsigned a;
    asm("{ .reg .u64 t; cvta.to.shared.u64 t, %1; cvt.u32.u64 %0, t; }"
        : "=r"(a) : "l"(p));
    return a;
}
__device__ __forceinline__ void cp16(unsigned saddr, const void* gaddr) {
    asm volatile("cp.async.cg.shared.global [%0], [%1], 16;"
                 :: "r"(saddr), "l"(gaddr));
}
__device__ __forceinline__ void ldsm_x4(unsigned addr, unsigned& r0, unsigned& r1,
                                        unsigned& r2, unsigned& r3) {
    asm volatile("ldmatrix.sync.aligned.m8n8.x4.shared.b16 {%0,%1,%2,%3}, [%4];"
                 : "=r"(r0), "=r"(r1), "=r"(r2), "=r"(r3) : "r"(addr));
}
__device__ __forceinline__ void mma_f16(float* c, const unsigned* a,
                                        unsigned b0, unsigned b1) {
    asm volatile(
        "mma.sync.aligned.m16n8k16.row.col.f32.f16.f16.f32 "
        "{%0,%1,%2,%3}, {%4,%5,%6,%7}, {%8,%9}, {%0,%1,%2,%3};"
        : "+f"(c[0]), "+f"(c[1]), "+f"(c[2]), "+f"(c[3])
        : "r"(a[0]), "r"(a[1]), "r"(a[2]), "r"(a[3]), "r"(b0), "r"(b1));
}

// fp32 -> fp16 conversion of all three GEMM inputs, one launch
__global__ __launch_bounds__(256) void tohalf_all_kernel(
    const float4* __restrict__ s0, __half2* __restrict__ d0, int n0,
    const float4* __restrict__ s1, __half2* __restrict__ d1, int n1,
    const float4* __restrict__ s2, __half2* __restrict__ d2, int n2)
{
    const int stride = gridDim.x * blockDim.x;
    const int t0 = blockIdx.x * blockDim.x + threadIdx.x;
    for (int i = t0; i < n0; i += stride) {
        float4 v = s0[i];
        d0[2 * i]     = __floats2half2_rn(v.x, v.y);
        d0[2 * i + 1] = __floats2half2_rn(v.z, v.w);
    }
    for (int i = t0; i < n1; i += stride) {
        float4 v = s1[i];
        d1[2 * i]     = __floats2half2_rn(v.x, v.y);
        d1[2 * i + 1] = __floats2half2_rn(v.z, v.w);
    }
    for (int i = t0; i < n2; i += stride) {
        float4 v = s2[i];
        d2[2 * i]     = __floats2half2_rn(v.x, v.y);
        d2[2 * i + 1] = __floats2half2_rn(v.z, v.w);
    }
}

// ===========================================================================
// fp16 mma.sync GEMM mainloop: 128x128x64 CTA tile, 128 threads = 4 warps
// (2x2 grid of 64x64 warp tiles -> smem-port/tensor ratio 1:1 vs 1.5:1 for
// the 8-warp/64x32 layout).  2-stage cp.async, prefetch-commit-before-wait.
// ===========================================================================
#define BM 128
#define BN 128
#define BK 64                               // halves of K per iter
#define PITCH 144                           // bytes per 64-half row (128+16)
#define TILE_B (BM * PITCH)                 // 18432 B per matrix buffer
#define GEMM_SMEM (4 * TILE_B)              // A0 A1 B0 B1 = 73728 B

// accumulates into acc[4][8][4] (warp tile 64x64)
__device__ __forceinline__ void gemm_mainloop(
    const __half* __restrict__ A, const __half* __restrict__ B,
    int Kd, int m0, int n0, unsigned sbase, int tid, float acc[4][8][4])
{
    const int lane = tid & 31;
    const int wid  = tid >> 5;
    const int warpM = wid >> 1;            // 0..1
    const int warpN = wid & 1;             // 0..1

    const unsigned sA[2] = { sbase, sbase + TILE_B };
    const unsigned sB[2] = { sbase + 2 * TILE_B, sbase + 3 * TILE_B };

    // cp.async: 1024 chunks(16B)/matrix, 8 per thread per matrix
    const int row_ld = tid >> 3;           // 0..15 (+16 per i)
    const int chk    = tid & 7;

    const int KT = Kd / BK;
    const __half* Aptr = A + (size_t)(m0 + row_ld) * Kd + chk * 8;
    const __half* Bptr = B + (size_t)(n0 + row_ld) * Kd + chk * 8;
    const size_t rstep = (size_t)16 * Kd;
    const unsigned ld_off = (unsigned)(row_ld * PITCH + chk * 16);

    {
#pragma unroll
        for (int i = 0; i < 8; i++) {
            cp16(sA[0] + ld_off + i * (16 * PITCH), Aptr + i * rstep);
            cp16(sB[0] + ld_off + i * (16 * PITCH), Bptr + i * rstep);
        }
        asm volatile("cp.async.commit_group;" ::: "memory");
    }

    const unsigned aRowOff = (unsigned)((warpM * 64 + (lane & 15)) * PITCH
                                        + (lane >> 4) * 16);
    const unsigned bRowOff = (unsigned)((warpN * 64 + (lane & 7)
                                         + ((lane >> 4) * 8)) * PITCH
                                        + ((lane >> 3) & 1) * 16);

    for (int kt = 0; kt < KT; kt++) {
        const int cur = kt & 1;
        if (kt + 1 < KT) {
            const int nxt = cur ^ 1;
            const __half* ap = Aptr + (kt + 1) * BK;
            const __half* bp = Bptr + (kt + 1) * BK;
#pragma unroll
            for (int i = 0; i < 8; i++) {
                cp16(sA[nxt] + ld_off + i * (16 * PITCH), ap + i * rstep);
                cp16(sB[nxt] + ld_off + i * (16 * PITCH), bp + i * rstep);
            }
            asm volatile("cp.async.commit_group;" ::: "memory");
            asm volatile("cp.async.wait_group 1;" ::: "memory");
        } else {
            asm volatile("cp.async.wait_group 0;" ::: "memory");
        }
        __syncthreads();

        const unsigned aBase = sA[cur] + aRowOff;
        const unsigned bBase = sB[cur] + bRowOff;

#pragma unroll
        for (int kk = 0; kk < 4; kk++) {
            unsigned af[4][4];
#pragma unroll
            for (int mt = 0; mt < 4; mt++)
                ldsm_x4(aBase + mt * (16 * PITCH) + kk * 32,
                        af[mt][0], af[mt][1], af[mt][2], af[mt][3]);
#pragma unroll
            for (int ntp = 0; ntp < 4; ntp++) {
                unsigned r0, r1, r2, r3;
                ldsm_x4(bBase + ntp * (16 * PITCH) + kk * 32, r0, r1, r2, r3);
#pragma unroll
                for (int mt = 0; mt < 4; mt++) {
                    mma_f16(acc[mt][2 * ntp],     af[mt], r0, r1);
                    mma_f16(acc[mt][2 * ntp + 1], af[mt], r2, r3);
                }
            }
        }
        __syncthreads();
    }
}

// ---------------------------------------------------------------------------
// Generic GEMM with fp32 output (output projection)
// ---------------------------------------------------------------------------
__global__ __launch_bounds__(128, 2) void gemm_f16mma(
    const __half* __restrict__ A, const __half* __restrict__ B,
    float* __restrict__ C, int Nd, int Kd)
{
    extern __shared__ char smem[];
    const unsigned sbase = smem_u32(smem);
    const int tid  = threadIdx.x;
    const int lane = tid & 31;
    const int wid  = tid >> 5;
    const int m0 = blockIdx.y * BM;
    const int n0 = blockIdx.x * BN;

    float acc[4][8][4];
#pragma unroll
    for (int a = 0; a < 4; a++)
#pragma unroll
        for (int b = 0; b < 8; b++)
#pragma unroll
            for (int c = 0; c < 4; c++) acc[a][b][c] = 0.0f;

    gemm_mainloop(A, B, Kd, m0, n0, sbase, tid, acc);

    const int rBase = m0 + (wid >> 1) * 64 + (lane >> 2);
    const int cBase = n0 + (wid & 1) * 64 + (lane & 3) * 2;
#pragma unroll
    for (int mt = 0; mt < 4; mt++)
#pragma unroll
        for (int nt = 0; nt < 8; nt++) {
            float* p0 = C + (size_t)(rBase + mt * 16) * Nd + cBase + nt * 8;
            float* p1 = C + (size_t)(rBase + mt * 16 + 8) * Nd + cBase + nt * 8;
            *(float2*)p0 = make_float2(acc[mt][nt][0], acc[mt][nt][1]);
            *(float2*)p1 = make_float2(acc[mt][nt][2], acc[mt][nt][3]);
        }
}

// ---------------------------------------------------------------------------
// QKV GEMM with fused RoPE + split + scale + V-transpose epilogue.
// kind = n0>>11 (0=q,1=k,2=v),  h = (n0&2047)>>7.
// ---------------------------------------------------------------------------
#define VT_SP 136     // smem transpose pitch in halves (128 + 8)

__global__ __launch_bounds__(128, 2) void gemm_qkv_fused(
    const __half* __restrict__ A, const __half* __restrict__ B)
{
    extern __shared__ char smem[];
    const unsigned sbase = smem_u32(smem);
    const int tid  = threadIdx.x;
    const int lane = tid & 31;
    const int wid  = tid >> 5;
    const int warpM = wid >> 1;
    const int warpN = wid & 1;
    const int m0 = blockIdx.y * BM;
    const int n0 = blockIdx.x * BN;

    float acc[4][8][4];
#pragma unroll
    for (int a = 0; a < 4; a++)
#pragma unroll
        for (int b = 0; b < 8; b++)
#pragma unroll
            for (int c = 0; c < 4; c++) acc[a][b][c] = 0.0f;

    gemm_mainloop(A, B, CDIM, m0, n0, sbase, tid, acc);

    const int kind = n0 >> 11;               // 0=q 1=k 2=v
    const int h    = (n0 & 2047) >> 7;
    const int rBase = m0 + warpM * 64 + (lane >> 2);   // global row
    const int cLoc  = warpN * 64 + (lane & 3) * 2;     // d within head (+nt*8)

    if (kind < 2) {
        // ---- RoPE rotation: only warpN==0 holds d<16 (nt=0 pairs nt=1)
        if (warpN == 0) {
            const int dlo = (lane & 3) * 2;   // 0,2,4,6 ; elements i=dlo, dlo+1
#pragma unroll
            for (int j = 0; j < 2; j++) {
                float fr = __powf(10000.0f, -(float)(dlo + j) * 0.125f);
#pragma unroll
                for (int mt = 0; mt < 4; mt++) {
                    int t0 = (rBase + mt * 16) & (SEQ - 1);
                    float s0, c0, s1, c1;
                    __sincosf((float)t0 * fr, &s0, &c0);
                    __sincosf((float)(t0 + 8) * fr, &s1, &c1);
                    float lo0 = acc[mt][0][j],     hi0 = acc[mt][1][j];
                    acc[mt][0][j]     = lo0 * c0 - hi0 * s0;
                    acc[mt][1][j]     = hi0 * c0 + lo0 * s0;
                    float lo1 = acc[mt][0][2 + j], hi1 = acc[mt][1][2 + j];
                    acc[mt][0][2 + j] = lo1 * c1 - hi1 * s1;
                    acc[mt][1][2 + j] = hi1 * c1 + lo1 * s1;
                }
            }
        }
        const float scale = (kind == 0) ? 0.08838834764831845f : 1.0f;
        __half* dst = (kind == 0) ? g_q : g_k;
#pragma unroll
        for (int mt = 0; mt < 4; mt++) {
            int r0 = rBase + mt * 16;
            int b0 = r0 >> 9, t0 = r0 & (SEQ - 1);
            size_t base = ((size_t)(b0 * NH + h) * SEQ + t0) * HD;
#pragma unroll
            for (int nt = 0; nt < 8; nt++) {
                int d = cLoc + nt * 8;
                *(__half2*)(dst + base + d) =
                    __floats2half2_rn(acc[mt][nt][0] * scale,
                                      acc[mt][nt][1] * scale);
                *(__half2*)(dst + base + 8 * HD + d) =
                    __floats2half2_rn(acc[mt][nt][2] * scale,
                                      acc[mt][nt][3] * scale);
            }
        }
    } else {
        // ---- V: smem transpose then coalesced fp16 stores to g_vT[bh][d][t]
        __half* vs = (__half*)smem;           // 128 x VT_SP halves = 34816 B
        const int tLoc = (rBase - m0);        // 0..119 (+8 half)
#pragma unroll
        for (int mt = 0; mt < 4; mt++) {
            int tl = tLoc + mt * 16;
#pragma unroll
            for (int nt = 0; nt < 8; nt++) {
                int d = cLoc + nt * 8;
                vs[d * VT_SP + tl]           = __float2half_rn(acc[mt][nt][0]);
                vs[(d + 1) * VT_SP + tl]     = __float2half_rn(acc[mt][nt][1]);
                vs[d * VT_SP + tl + 8]       = __float2half_rn(acc[mt][nt][2]);
                vs[(d + 1) * VT_SP + tl + 8] = __float2half_rn(acc[mt][nt][3]);
            }
        }
        __syncthreads();
        const int b = m0 >> 9, t0g = m0 & (SEQ - 1);
        __half* vbase = g_vT + ((size_t)(b * NH + h) * HD) * SEQ + t0g;
#pragma unroll
        for (int i = 0; i < 16; i++) {
            int id = tid + i * 128;           // 2048 chunks of 8 halves
            int dr = id >> 4, ch = id & 15;
            *(uint4*)(vbase + (size_t)dr * SEQ + ch * 8) =
                *(uint4*)(vs + dr * VT_SP + ch * 8);
        }
    }
}

// ===========================================================================
// Flash attention, fp16 mma: CTA = 64 queries x 1 (b,h), Bc=32 keys.
// ===========================================================================
#define QK_PITCH 272
#define VT_PITCH 80
#define OFF_Q    0
#define OFF_K0   17408
#define OFF_K1   26112
#define OFF_V0   34816
#define OFF_V1   45056
#define OFF_P    55296
#define ATTN_SMEM 60416

__global__ __launch_bounds__(128, 3) void fattn_kernel()
{
    extern __shared__ char smem[];
    const unsigned sb = smem_u32(smem);
    const int bh = blockIdx.y;
    const int qt = blockIdx.x;
    const int q0 = qt * 64;
    const int jmax = 2 * qt + 1;
    const int tid = threadIdx.x;
    const int lane = tid & 31;
    const int wq = tid >> 5;

    {
        const __half* qg = g_q + ((size_t)bh * SEQ + q0) * HD;
#pragma unroll
        for (int i = 0; i < 8; i++) {
            int id = tid + i * 128;
            int row = id >> 4, c16 = id & 15;
            cp16(sb + OFF_Q + row * QK_PITCH + c16 * 16, qg + row * HD + c16 * 8);
        }
        asm volatile("cp.async.commit_group;" ::: "memory");
        asm volatile("cp.async.wait_group 0;" ::: "memory");
        __syncthreads();
    }
    unsigned qf[8][4];
    {
        unsigned qaddr = sb + OFF_Q + (wq * 16 + (lane & 15)) * QK_PITCH
                       + (lane >> 4) * 16;
#pragma unroll
        for (int kk = 0; kk < 8; kk++)
            ldsm_x4(qaddr + kk * 32, qf[kk][0], qf[kk][1], qf[kk][2], qf[kk][3]);
    }
    __syncthreads();

    float m1 = -1e30f, m2 = -1e30f, l1 = 0.0f, l2 = 0.0f;
    float oacc[16][4];
#pragma unroll
    for (int nt = 0; nt < 16; nt++)
#pragma unroll
        for (int c = 0; c < 4; c++) oacc[nt][c] = 0.0f;

    auto load_tile = [&](int j) {
        unsigned kb = sb + ((j & 1) ? OFF_K1 : OFF_K0);
        unsigned vb = sb + ((j & 1) ? OFF_V1 : OFF_V0);
        const __half* kg = g_k + ((size_t)bh * SEQ + j * 32) * HD;
        const __half* vg = g_vT + (size_t)bh * HD * SEQ + j * 32;
#pragma unroll
        for (int i = 0; i < 4; i++) {
            int id = tid + i * 128;
            int kr = id >> 4, kc = id & 15;
            cp16(kb + kr * QK_PITCH + kc * 16, kg + kr * HD + kc * 8);
            int vr = id >> 2, vc = id & 3;
            cp16(vb + vr * VT_PITCH + vc * 16, vg + (size_t)vr * SEQ + vc * 8);
        }
        asm volatile("cp.async.commit_group;" ::: "memory");
    };

    load_tile(0);

    const int rowg1 = q0 + wq * 16 + (lane >> 2);
    const unsigned bOff = (unsigned)(((lane & 7) + ((lane >> 4) * 8)) * QK_PITCH
                                     + ((lane >> 3) & 1) * 16);
    const unsigned vOff = (unsigned)(((lane & 7) + ((lane >> 4) * 8)) * VT_PITCH
                                     + ((lane >> 3) & 1) * 16);

    for (int j = 0; j <= jmax; j++) {
        asm volatile("cp.async.wait_group 0;" ::: "memory");
        __syncthreads();
        if (j < jmax) load_tile(j + 1);

        float sacc[4][4];
#pragma unroll
        for (int nt = 0; nt < 4; nt++)
#pragma unroll
            for (int c = 0; c < 4; c++) sacc[nt][c] = 0.0f;

        const unsigned kbase = sb + ((j & 1) ? OFF_K1 : OFF_K0) + bOff;
#pragma unroll
        for (int kk = 0; kk < 8; kk++) {
            unsigned bf[4][2];
#pragma unroll
            for (int ntp = 0; ntp < 2; ntp++) {
                unsigned r0, r1, r2, r3;
                ldsm_x4(kbase + ntp * (16 * QK_PITCH) + kk * 32, r0, r1, r2, r3);
                bf[2 * ntp][0] = r0;     bf[2 * ntp][1] = r1;
                bf[2 * ntp + 1][0] = r2; bf[2 * ntp + 1][1] = r3;
            }
#pragma unroll
            for (int nt = 0; nt < 4; nt++)
                mma_f16(sacc[nt], qf[kk], bf[nt][0], bf[nt][1]);
        }

        if (j * 32 + 31 > q0 + wq * 16) {
#pragma unroll
            for (int nt = 0; nt < 4; nt++) {
                int colb = j * 32 + nt * 8 + (lane & 3) * 2;
                if (colb     > rowg1)     sacc[nt][0] = -1e30f;
                if (colb + 1 > rowg1)     sacc[nt][1] = -1e30f;
                if (colb     > rowg1 + 8) sacc[nt][2] = -1e30f;
                if (colb + 1 > rowg1 + 8) sacc[nt][3] = -1e30f;
            }
        }

        float tm1 = -1e30f, tm2 = -1e30f;
#pragma unroll
        for (int nt = 0; nt < 4; nt++) {
            tm1 = fmaxf(tm1, fmaxf(sacc[nt][0], sacc[nt][1]));
            tm2 = fmaxf(tm2, fmaxf(sacc[nt][2], sacc[nt][3]));
        }
        tm1 = fmaxf(tm1, __shfl_xor_sync(0xffffffffu, tm1, 1));
        tm1 = fmaxf(tm1, __shfl_xor_sync(0xffffffffu, tm1, 2));
        tm2 = fmaxf(tm2, __shfl_xor_sync(0xffffffffu, tm2, 1));
        tm2 = fmaxf(tm2, __shfl_xor_sync(0xffffffffu, tm2, 2));

        float m1n = fmaxf(m1, tm1), m2n = fmaxf(m2, tm2);
        float corr1 = __expf(m1 - m1n), corr2 = __expf(m2 - m2n);
        m1 = m1n; m2 = m2n;

        float rs1 = 0.0f, rs2 = 0.0f;
#pragma unroll
        for (int nt = 0; nt < 4; nt++) {
            sacc[nt][0] = __expf(sacc[nt][0] - m1n);
            sacc[nt][1] = __expf(sacc[nt][1] - m1n);
            sacc[nt][2] = __expf(sacc[nt][2] - m2n);
            sacc[nt][3] = __expf(sacc[nt][3] - m2n);
            rs1 += sacc[nt][0] + sacc[nt][1];
            rs2 += sacc[nt][2] + sacc[nt][3];
        }
        rs1 += __shfl_xor_sync(0xffffffffu, rs1, 1);
        rs1 += __shfl_xor_sync(0xffffffffu, rs1, 2);
        rs2 += __shfl_xor_sync(0xffffffffu, rs2, 1);
        rs2 += __shfl_xor_sync(0xffffffffu, rs2, 2);
        l1 = l1 * corr1 + rs1;
        l2 = l2 * corr2 + rs2;

#pragma unroll
        for (int nt = 0; nt < 16; nt++) {
            oacc[nt][0] *= corr1; oacc[nt][1] *= corr1;
            oacc[nt][2] *= corr2; oacc[nt][3] *= corr2;
        }

        {
            int pr1 = wq * 16 + (lane >> 2);
            int pc = (lane & 3) * 2;
#pragma unroll
            for (int nt = 0; nt < 4; nt++) {
                *(__half2*)(smem + OFF_P + pr1 * VT_PITCH + (nt * 8 + pc) * 2) =
                    __floats2half2_rn(sacc[nt][0], sacc[nt][1]);
                *(__half2*)(smem + OFF_P + (pr1 + 8) * VT_PITCH + (nt * 8 + pc) * 2) =
                    __floats2half2_rn(sacc[nt][2], sacc[nt][3]);
            }
        }
        __syncthreads();

        const unsigned vbase = sb + ((j & 1) ? OFF_V1 : OFF_V0) + vOff;
        const unsigned paddr = sb + OFF_P + (wq * 16 + (lane & 15)) * VT_PITCH
                             + (lane >> 4) * 16;
#pragma unroll
        for (int kk2 = 0; kk2 < 2; kk2++) {
            unsigned pf[4];
            ldsm_x4(paddr + kk2 * 32, pf[0], pf[1], pf[2], pf[3]);
#pragma unroll
            for (int ntp = 0; ntp < 8; ntp++) {
                unsigned r0, r1, r2, r3;
                ldsm_x4(vbase + ntp * (16 * VT_PITCH) + kk2 * 32, r0, r1, r2, r3);
                mma_f16(oacc[2 * ntp],     pf, r0, r1);
                mma_f16(oacc[2 * ntp + 1], pf, r2, r3);
            }
        }
        __syncthreads();
    }

    float inv1 = 1.0f / l1, inv2 = 1.0f / l2;
    int b = bh >> 4, h = bh & 15;
    int row1 = q0 + wq * 16 + (lane >> 2);
#pragma unroll
    for (int nt = 0; nt < 16; nt++) {
        int d = nt * 8 + (lane & 3) * 2;
        __half* p0 = g_y + (size_t)(b * SEQ + row1) * CDIM + h * HD + d;
        __half* p1 = g_y + (size_t)(b * SEQ + row1 + 8) * CDIM + h * HD + d;
        *(__half2*)p0 = __floats2half2_rn(oacc[nt][0] * inv1, oacc[nt][1] * inv1);
        *(__half2*)p1 = __floats2half2_rn(oacc[nt][2] * inv2, oacc[nt][3] * inv2);
    }
}

// ---------------------------------------------------------------------------
extern "C" void kernel_launch(void* const* d_in, const int* in_sizes, int n_in,
                              void* d_out, int out_size)
{
    (void)in_sizes; (void)n_in; (void)out_size;
    const float* x    = (const float*)d_in[0];
    const float* Wqkv = (const float*)d_in[1];
    const float* Wout = (const float*)d_in[2];
    float* out = (float*)d_out;

    __half *y_p, *xh_p, *w1_p, *w2_p;
    cudaGetSymbolAddress((void**)&y_p,  g_y);
    cudaGetSymbolAddress((void**)&xh_p, g_xh);
    cudaGetSymbolAddress((void**)&w1_p, g_w1);
    cudaGetSymbolAddress((void**)&w2_p, g_w2);

    cudaFuncSetAttribute(gemm_f16mma,
                         cudaFuncAttributeMaxDynamicSharedMemorySize, GEMM_SMEM);
    cudaFuncSetAttribute(gemm_qkv_fused,
                         cudaFuncAttributeMaxDynamicSharedMemorySize, GEMM_SMEM);
    cudaFuncSetAttribute(fattn_kernel,
                         cudaFuncAttributeMaxDynamicSharedMemorySize, ATTN_SMEM);

    // 0) fp32 -> fp16 GEMM inputs (single launch)
    tohalf_all_kernel<<<2368, 256>>>(
        (const float4*)x,    (__half2*)xh_p, MTOK * CDIM / 4,
        (const float4*)Wqkv, (__half2*)w1_p, F3 * CDIM / 4,
        (const float4*)Wout, (__half2*)w2_p, CDIM * CDIM / 4);

    // 1) qkv GEMM with fused RoPE/split/scale/V-transpose
    gemm_qkv_fused<<<dim3(F3 / BN, MTOK / BM), 128, GEMM_SMEM>>>(xh_p, w1_p);

    // 2) flash attention (fp16 mma) -> y
    fattn_kernel<<<dim3(SEQ / 64, BATCH * NH), 128, ATTN_SMEM>>>();

    // 3) out = y @ Wout^T  (fp32 output)
    gemm_f16mma<<<dim3(CDIM / BN, MTOK / BM), 128, GEMM_SMEM>>>(y_p, w2_p, out, CDIM, CDIM);
}

// round 14
// speedup vs baseline: 1.1025x; 1.1025x over previous
#include <cuda_runtime.h>
#include <cuda_fp16.h>
#include <math.h>

#define BATCH 8
#define SEQ   512
#define CDIM  2048
#define NH    16
#define HD    128
#define MTOK  (BATCH*SEQ)      // 4096
#define F3    (3*CDIM)         // 6144

// Scratch (static device arrays; no allocation anywhere)
__device__ __half g_q [BATCH*NH*SEQ*HD];    // [bh][t][d] scaled fp16 (rope'd)
__device__ __half g_k [BATCH*NH*SEQ*HD];    // [bh][t][d] fp16 (rope'd)
__device__ __half g_vT[BATCH*NH*HD*SEQ];    // [bh][d][t] fp16 (transposed)
__device__ __half g_y [MTOK * CDIM];        // [b,t,C] fp16
__device__ __half g_xh[MTOK * CDIM];        // fp16 x
__device__ __half g_w1[F3 * CDIM];          // fp16 Wqkv
__device__ __half g_w2[CDIM * CDIM];        // fp16 Wout

// ---------------------------------------------------------------------------
__device__ __forceinline__ unsigned smem_u32(const void* p) {
    unsigned a;
    asm("{ .reg .u64 t; cvta.to.shared.u64 t, %1; cvt.u32.u64 %0, t; }"
        : "=r"(a) : "l"(p));
    return a;
}
__device__ __forceinline__ void cp16(unsigned saddr, const void* gaddr) {
    asm volatile("cp.async.cg.shared.global [%0], [%1], 16;"
                 :: "r"(saddr), "l"(gaddr));
}
__device__ __forceinline__ void ldsm_x4(unsigned addr, unsigned& r0, unsigned& r1,
                                        unsigned& r2, unsigned& r3) {
    asm volatile("ldmatrix.sync.aligned.m8n8.x4.shared.b16 {%0,%1,%2,%3}, [%4];"
                 : "=r"(r0), "=r"(r1), "=r"(r2), "=r"(r3) : "r"(addr));
}
__device__ __forceinline__ void mma_f16(float* c, const unsigned* a,
                                        unsigned b0, unsigned b1) {
    asm volatile(
        "mma.sync.aligned.m16n8k16.row.col.f32.f16.f16.f32 "
        "{%0,%1,%2,%3}, {%4,%5,%6,%7}, {%8,%9}, {%0,%1,%2,%3};"
        : "+f"(c[0]), "+f"(c[1]), "+f"(c[2]), "+f"(c[3])
        : "r"(a[0]), "r"(a[1]), "r"(a[2]), "r"(a[3]), "r"(b0), "r"(b1));
}

// fp32 -> fp16 conversion of all three GEMM inputs, one launch
__global__ __launch_bounds__(256) void tohalf_all_kernel(
    const float4* __restrict__ s0, __half2* __restrict__ d0, int n0,
    const float4* __restrict__ s1, __half2* __restrict__ d1, int n1,
    const float4* __restrict__ s2, __half2* __restrict__ d2, int n2)
{
    const int stride = gridDim.x * blockDim.x;
    const int t0 = blockIdx.x * blockDim.x + threadIdx.x;
    for (int i = t0; i < n0; i += stride) {
        float4 v = s0[i];
        d0[2 * i]     = __floats2half2_rn(v.x, v.y);
        d0[2 * i + 1] = __floats2half2_rn(v.z, v.w);
    }
    for (int i = t0; i < n1; i += stride) {
        float4 v = s1[i];
        d1[2 * i]     = __floats2half2_rn(v.x, v.y);
        d1[2 * i + 1] = __floats2half2_rn(v.z, v.w);
    }
    for (int i = t0; i < n2; i += stride) {
        float4 v = s2[i];
        d2[2 * i]     = __floats2half2_rn(v.x, v.y);
        d2[2 * i + 1] = __floats2half2_rn(v.z, v.w);
    }
}

// ===========================================================================
// fp16 mma.sync GEMM mainloop: 128x128x64 CTA tile, 256 threads = 8 warps
// (2x4 grid, 64x32 warp tiles — proven best), 3-stage smem, ONE barrier per
// kt: wait -> sync -> contiguous prefetch(kt+2) -> compute.  Race-free:
// stage (kt+2)%3 was consumed at kt-1 and every warp passed this kt's
// barrier (so finished kt-1) before any cp.async writes land there.
// ===========================================================================
#define BM 128
#define BN 128
#define BK 64                               // halves of K per iter
#define PITCH 144                           // bytes per 64-half row (128+16)
#define TILE_B (BM * PITCH)                 // 18432 B per matrix per stage
#define STAGE_B (2 * TILE_B)                // A+B per stage = 36864
#define GEMM_SMEM (3 * STAGE_B)             // 110592 B; 2 CTAs = 216 KB

__device__ __forceinline__ void gemm_mainloop(
    const __half* __restrict__ A, const __half* __restrict__ B,
    int Kd, int m0, int n0, unsigned sbase, int tid, float acc[4][4][4])
{
    const int lane = tid & 31;
    const int wid  = tid >> 5;
    const int warpM = wid >> 2;            // 0..1
    const int warpN = wid & 3;             // 0..3

    // cp.async: 1024 chunks(16B)/matrix, 4 per thread per matrix
    const int row_ld = tid >> 3;           // 0..31 (+32 per i)
    const int chk    = tid & 7;

    const int KT = Kd / BK;
    const __half* Aptr = A + (size_t)(m0 + row_ld) * Kd + chk * 8;
    const __half* Bptr = B + (size_t)(n0 + row_ld) * Kd + chk * 8;
    const size_t rstep = (size_t)32 * Kd;
    const unsigned ld_off = (unsigned)(row_ld * PITCH + chk * 16);

    // ---- prologue: stages 0,1
#pragma unroll
    for (int pk = 0; pk < 2; pk++) {
        unsigned sA = sbase + pk * STAGE_B + ld_off;
        unsigned sB = sA + TILE_B;
        const __half* ap = Aptr + pk * BK;
        const __half* bp = Bptr + pk * BK;
#pragma unroll
        for (int i = 0; i < 4; i++) {
            cp16(sA + i * (32 * PITCH), ap + i * rstep);
            cp16(sB + i * (32 * PITCH), bp + i * rstep);
        }
        asm volatile("cp.async.commit_group;" ::: "memory");
    }

    const unsigned aRowOff = (unsigned)((warpM * 64 + (lane & 15)) * PITCH
                                        + (lane >> 4) * 16);
    const unsigned bRowOff = (unsigned)((warpN * 32 + (lane & 7)
                                         + ((lane >> 4) * 8)) * PITCH
                                        + ((lane >> 3) & 1) * 16);

    int pf_st = 2;    // stage receiving kt+2's data
    int cs_st = 0;    // stage consumed at kt

    for (int kt = 0; kt < KT; kt++) {
        if (kt < KT - 2)
            asm volatile("cp.async.wait_group 1;" ::: "memory");
        else
            asm volatile("cp.async.wait_group 0;" ::: "memory");
        __syncthreads();                     // the ONLY barrier per kt

        // contiguous prefetch block for kt+2 (after barrier => race-free)
        if (kt + 2 < KT) {
            unsigned sA = sbase + pf_st * STAGE_B + ld_off;
            unsigned sB = sA + TILE_B;
            const __half* ap = Aptr + (kt + 2) * BK;
            const __half* bp = Bptr + (kt + 2) * BK;
#pragma unroll
            for (int i = 0; i < 4; i++) {
                cp16(sA + i * (32 * PITCH), ap + i * rstep);
                cp16(sB + i * (32 * PITCH), bp + i * rstep);
            }
            asm volatile("cp.async.commit_group;" ::: "memory");
        }
        if (++pf_st == 3) pf_st = 0;

        const unsigned aBase = sbase + cs_st * STAGE_B + aRowOff;
        const unsigned bBase = sbase + cs_st * STAGE_B + TILE_B + bRowOff;
        if (++cs_st == 3) cs_st = 0;

#pragma unroll
        for (int kk = 0; kk < 4; kk++) {
            unsigned af[4][4];
#pragma unroll
            for (int mt = 0; mt < 4; mt++)
                ldsm_x4(aBase + mt * (16 * PITCH) + kk * 32,
                        af[mt][0], af[mt][1], af[mt][2], af[mt][3]);
            unsigned bf[4][2];
#pragma unroll
            for (int ntp = 0; ntp < 2; ntp++) {
                unsigned r0, r1, r2, r3;
                ldsm_x4(bBase + ntp * (16 * PITCH) + kk * 32, r0, r1, r2, r3);
                bf[2 * ntp][0] = r0;     bf[2 * ntp][1] = r1;
                bf[2 * ntp + 1][0] = r2; bf[2 * ntp + 1][1] = r3;
            }
#pragma unroll
            for (int mt = 0; mt < 4; mt++)
#pragma unroll
                for (int nt = 0; nt < 4; nt++)
                    mma_f16(acc[mt][nt], af[mt], bf[nt][0], bf[nt][1]);
        }
        // no bottom barrier: next iteration's top barrier orders reuse
    }
}

// ---------------------------------------------------------------------------
// Generic GEMM with fp32 output (output projection)
// ---------------------------------------------------------------------------
__global__ __launch_bounds__(256, 2) void gemm_f16mma(
    const __half* __restrict__ A, const __half* __restrict__ B,
    float* __restrict__ C, int Nd, int Kd)
{
    extern __shared__ char smem[];
    const unsigned sbase = smem_u32(smem);
    const int tid  = threadIdx.x;
    const int lane = tid & 31;
    const int wid  = tid >> 5;
    const int m0 = blockIdx.y * BM;
    const int n0 = blockIdx.x * BN;

    float acc[4][4][4];
#pragma unroll
    for (int a = 0; a < 4; a++)
#pragma unroll
        for (int b = 0; b < 4; b++)
#pragma unroll
            for (int c = 0; c < 4; c++) acc[a][b][c] = 0.0f;

    gemm_mainloop(A, B, Kd, m0, n0, sbase, tid, acc);

    const int rBase = m0 + (wid >> 2) * 64 + (lane >> 2);
    const int cBase = n0 + (wid & 3) * 32 + (lane & 3) * 2;
#pragma unroll
    for (int mt = 0; mt < 4; mt++)
#pragma unroll
        for (int nt = 0; nt < 4; nt++) {
            float* p0 = C + (size_t)(rBase + mt * 16) * Nd + cBase + nt * 8;
            float* p1 = C + (size_t)(rBase + mt * 16 + 8) * Nd + cBase + nt * 8;
            *(float2*)p0 = make_float2(acc[mt][nt][0], acc[mt][nt][1]);
            *(float2*)p1 = make_float2(acc[mt][nt][2], acc[mt][nt][3]);
        }
}

// ---------------------------------------------------------------------------
// QKV GEMM with fused RoPE + split + scale + V-transpose epilogue.
// kind = n0>>11 (0=q,1=k,2=v),  h = (n0&2047)>>7.
// ---------------------------------------------------------------------------
#define VT_SP 136     // smem transpose pitch in halves (128 + 8)

__global__ __launch_bounds__(256, 2) void gemm_qkv_fused(
    const __half* __restrict__ A, const __half* __restrict__ B)
{
    extern __shared__ char smem[];
    const unsigned sbase = smem_u32(smem);
    const int tid  = threadIdx.x;
    const int lane = tid & 31;
    const int wid  = tid >> 5;
    const int warpM = wid >> 2;
    const int warpN = wid & 3;
    const int m0 = blockIdx.y * BM;
    const int n0 = blockIdx.x * BN;

    float acc[4][4][4];
#pragma unroll
    for (int a = 0; a < 4; a++)
#pragma unroll
        for (int b = 0; b < 4; b++)
#pragma unroll
            for (int c = 0; c < 4; c++) acc[a][b][c] = 0.0f;

    gemm_mainloop(A, B, CDIM, m0, n0, sbase, tid, acc);

    const int kind = n0 >> 11;               // 0=q 1=k 2=v
    const int h    = (n0 & 2047) >> 7;
    const int rBase = m0 + warpM * 64 + (lane >> 2);   // global row
    const int cLoc  = warpN * 32 + (lane & 3) * 2;     // d within head (+nt*8)

    if (kind < 2) {
        // ---- RoPE rotation: only warpN==0 holds d<16 (nt=0 pairs nt=1)
        if (warpN == 0) {
            const int dlo = (lane & 3) * 2;   // 0,2,4,6 ; elements i=dlo, dlo+1
#pragma unroll
            for (int j = 0; j < 2; j++) {
                float fr = __powf(10000.0f, -(float)(dlo + j) * 0.125f);
#pragma unroll
                for (int mt = 0; mt < 4; mt++) {
                    int t0 = (rBase + mt * 16) & (SEQ - 1);
                    float s0, c0, s1, c1;
                    __sincosf((float)t0 * fr, &s0, &c0);
                    __sincosf((float)(t0 + 8) * fr, &s1, &c1);
                    float lo0 = acc[mt][0][j],     hi0 = acc[mt][1][j];
                    acc[mt][0][j]     = lo0 * c0 - hi0 * s0;
                    acc[mt][1][j]     = hi0 * c0 + lo0 * s0;
                    float lo1 = acc[mt][0][2 + j], hi1 = acc[mt][1][2 + j];
                    acc[mt][0][2 + j] = lo1 * c1 - hi1 * s1;
                    acc[mt][1][2 + j] = hi1 * c1 + lo1 * s1;
                }
            }
        }
        const float scale = (kind == 0) ? 0.08838834764831845f : 1.0f;
        __half* dst = (kind == 0) ? g_q : g_k;
#pragma unroll
        for (int mt = 0; mt < 4; mt++) {
            int r0 = rBase + mt * 16;
            int b0 = r0 >> 9, t0 = r0 & (SEQ - 1);
            size_t base = ((size_t)(b0 * NH + h) * SEQ + t0) * HD;
#pragma unroll
            for (int nt = 0; nt < 4; nt++) {
                int d = cLoc + nt * 8;
                *(__half2*)(dst + base + d) =
                    __floats2half2_rn(acc[mt][nt][0] * scale,
                                      acc[mt][nt][1] * scale);
                *(__half2*)(dst + base + 8 * HD + d) =
                    __floats2half2_rn(acc[mt][nt][2] * scale,
                                      acc[mt][nt][3] * scale);
            }
        }
    } else {
        // ---- V: smem transpose then coalesced fp16 stores to g_vT[bh][d][t]
        __syncthreads();                      // tile bufs done being read
        __half* vs = (__half*)smem;           // 128 x VT_SP halves = 34816 B
        const int tLoc = (rBase - m0);        // 0..119 (+8 half)
#pragma unroll
        for (int mt = 0; mt < 4; mt++) {
            int tl = tLoc + mt * 16;
#pragma unroll
            for (int nt = 0; nt < 4; nt++) {
                int d = cLoc + nt * 8;
                vs[d * VT_SP + tl]           = __float2half_rn(acc[mt][nt][0]);
                vs[(d + 1) * VT_SP + tl]     = __float2half_rn(acc[mt][nt][1]);
                vs[d * VT_SP + tl + 8]       = __float2half_rn(acc[mt][nt][2]);
                vs[(d + 1) * VT_SP + tl + 8] = __float2half_rn(acc[mt][nt][3]);
            }
        }
        __syncthreads();
        const int b = m0 >> 9, t0g = m0 & (SEQ - 1);
        __half* vbase = g_vT + ((size_t)(b * NH + h) * HD) * SEQ + t0g;
#pragma unroll
        for (int i = 0; i < 8; i++) {
            int id = tid + i * 256;           // 2048 chunks of 8 halves
            int dr = id >> 4, ch = id & 15;
            *(uint4*)(vbase + (size_t)dr * SEQ + ch * 8) =
                *(uint4*)(vs + dr * VT_SP + ch * 8);
        }
    }
}

// ===========================================================================
// Flash attention, fp16 mma: CTA = 64 queries x 1 (b,h), Bc=32 keys.
// ===========================================================================
#define QK_PITCH 272
#define VT_PITCH 80
#define OFF_Q    0
#define OFF_K0   17408
#define OFF_K1   26112
#define OFF_V0   34816
#define OFF_V1   45056
#define OFF_P    55296
#define ATTN_SMEM 60416

__global__ __launch_bounds__(128, 3) void fattn_kernel()
{
    extern __shared__ char smem[];
    const unsigned sb = smem_u32(smem);
    const int bh = blockIdx.y;
    const int qt = blockIdx.x;
    const int q0 = qt * 64;
    const int jmax = 2 * qt + 1;
    const int tid = threadIdx.x;
    const int lane = tid & 31;
    const int wq = tid >> 5;

    {
        const __half* qg = g_q + ((size_t)bh * SEQ + q0) * HD;
#pragma unroll
        for (int i = 0; i < 8; i++) {
            int id = tid + i * 128;
            int row = id >> 4, c16 = id & 15;
            cp16(sb + OFF_Q + row * QK_PITCH + c16 * 16, qg + row * HD + c16 * 8);
        }
        asm volatile("cp.async.commit_group;" ::: "memory");
        asm volatile("cp.async.wait_group 0;" ::: "memory");
        __syncthreads();
    }
    unsigned qf[8][4];
    {
        unsigned qaddr = sb + OFF_Q + (wq * 16 + (lane & 15)) * QK_PITCH
                       + (lane >> 4) * 16;
#pragma unroll
        for (int kk = 0; kk < 8; kk++)
            ldsm_x4(qaddr + kk * 32, qf[kk][0], qf[kk][1], qf[kk][2], qf[kk][3]);
    }
    __syncthreads();

    float m1 = -1e30f, m2 = -1e30f, l1 = 0.0f, l2 = 0.0f;
    float oacc[16][4];
#pragma unroll
    for (int nt = 0; nt < 16; nt++)
#pragma unroll
        for (int c = 0; c < 4; c++) oacc[nt][c] = 0.0f;

    auto load_tile = [&](int j) {
        unsigned kb = sb + ((j & 1) ? OFF_K1 : OFF_K0);
        unsigned vb = sb + ((j & 1) ? OFF_V1 : OFF_V0);
        const __half* kg = g_k + ((size_t)bh * SEQ + j * 32) * HD;
        const __half* vg = g_vT + (size_t)bh * HD * SEQ + j * 32;
#pragma unroll
        for (int i = 0; i < 4; i++) {
            int id = tid + i * 128;
            int kr = id >> 4, kc = id & 15;
            cp16(kb + kr * QK_PITCH + kc * 16, kg + kr * HD + kc * 8);
            int vr = id >> 2, vc = id & 3;
            cp16(vb + vr * VT_PITCH + vc * 16, vg + (size_t)vr * SEQ + vc * 8);
        }
        asm volatile("cp.async.commit_group;" ::: "memory");
    };

    load_tile(0);

    const int rowg1 = q0 + wq * 16 + (lane >> 2);
    const unsigned bOff = (unsigned)(((lane & 7) + ((lane >> 4) * 8)) * QK_PITCH
                                     + ((lane >> 3) & 1) * 16);
    const unsigned vOff = (unsigned)(((lane & 7) + ((lane >> 4) * 8)) * VT_PITCH
                                     + ((lane >> 3) & 1) * 16);

    for (int j = 0; j <= jmax; j++) {
        asm volatile("cp.async.wait_group 0;" ::: "memory");
        __syncthreads();
        if (j < jmax) load_tile(j + 1);

        float sacc[4][4];
#pragma unroll
        for (int nt = 0; nt < 4; nt++)
#pragma unroll
            for (int c = 0; c < 4; c++) sacc[nt][c] = 0.0f;

        const unsigned kbase = sb + ((j & 1) ? OFF_K1 : OFF_K0) + bOff;
#pragma unroll
        for (int kk = 0; kk < 8; kk++) {
            unsigned bf[4][2];
#pragma unroll
            for (int ntp = 0; ntp < 2; ntp++) {
                unsigned r0, r1, r2, r3;
                ldsm_x4(kbase + ntp * (16 * QK_PITCH) + kk * 32, r0, r1, r2, r3);
                bf[2 * ntp][0] = r0;     bf[2 * ntp][1] = r1;
                bf[2 * ntp + 1][0] = r2; bf[2 * ntp + 1][1] = r3;
            }
#pragma unroll
            for (int nt = 0; nt < 4; nt++)
                mma_f16(sacc[nt], qf[kk], bf[nt][0], bf[nt][1]);
        }

        if (j * 32 + 31 > q0 + wq * 16) {
#pragma unroll
            for (int nt = 0; nt < 4; nt++) {
                int colb = j * 32 + nt * 8 + (lane & 3) * 2;
                if (colb     > rowg1)     sacc[nt][0] = -1e30f;
                if (colb + 1 > rowg1)     sacc[nt][1] = -1e30f;
                if (colb     > rowg1 + 8) sacc[nt][2] = -1e30f;
                if (colb + 1 > rowg1 + 8) sacc[nt][3] = -1e30f;
            }
        }

        float tm1 = -1e30f, tm2 = -1e30f;
#pragma unroll
        for (int nt = 0; nt < 4; nt++) {
            tm1 = fmaxf(tm1, fmaxf(sacc[nt][0], sacc[nt][1]));
            tm2 = fmaxf(tm2, fmaxf(sacc[nt][2], sacc[nt][3]));
        }
        tm1 = fmaxf(tm1, __shfl_xor_sync(0xffffffffu, tm1, 1));
        tm1 = fmaxf(tm1, __shfl_xor_sync(0xffffffffu, tm1, 2));
        tm2 = fmaxf(tm2, __shfl_xor_sync(0xffffffffu, tm2, 1));
        tm2 = fmaxf(tm2, __shfl_xor_sync(0xffffffffu, tm2, 2));

        float m1n = fmaxf(m1, tm1), m2n = fmaxf(m2, tm2);
        float corr1 = __expf(m1 - m1n), corr2 = __expf(m2 - m2n);
        m1 = m1n; m2 = m2n;

        float rs1 = 0.0f, rs2 = 0.0f;
#pragma unroll
        for (int nt = 0; nt < 4; nt++) {
            sacc[nt][0] = __expf(sacc[nt][0] - m1n);
            sacc[nt][1] = __expf(sacc[nt][1] - m1n);
            sacc[nt][2] = __expf(sacc[nt][2] - m2n);
            sacc[nt][3] = __expf(sacc[nt][3] - m2n);
            rs1 += sacc[nt][0] + sacc[nt][1];
            rs2 += sacc[nt][2] + sacc[nt][3];
        }
        rs1 += __shfl_xor_sync(0xffffffffu, rs1, 1);
        rs1 += __shfl_xor_sync(0xffffffffu, rs1, 2);
        rs2 += __shfl_xor_sync(0xffffffffu, rs2, 1);
        rs2 += __shfl_xor_sync(0xffffffffu, rs2, 2);
        l1 = l1 * corr1 + rs1;
        l2 = l2 * corr2 + rs2;

#pragma unroll
        for (int nt = 0; nt < 16; nt++) {
            oacc[nt][0] *= corr1; oacc[nt][1] *= corr1;
            oacc[nt][2] *= corr2; oacc[nt][3] *= corr2;
        }

        {
            int pr1 = wq * 16 + (lane >> 2);
            int pc = (lane & 3) * 2;
#pragma unroll
            for (int nt = 0; nt < 4; nt++) {
                *(__half2*)(smem + OFF_P + pr1 * VT_PITCH + (nt * 8 + pc) * 2) =
                    __floats2half2_rn(sacc[nt][0], sacc[nt][1]);
                *(__half2*)(smem + OFF_P + (pr1 + 8) * VT_PITCH + (nt * 8 + pc) * 2) =
                    __floats2half2_rn(sacc[nt][2], sacc[nt][3]);
            }
        }
        __syncthreads();

        const unsigned vbase = sb + ((j & 1) ? OFF_V1 : OFF_V0) + vOff;
        const unsigned paddr = sb + OFF_P + (wq * 16 + (lane & 15)) * VT_PITCH
                             + (lane >> 4) * 16;
#pragma unroll
        for (int kk2 = 0; kk2 < 2; kk2++) {
            unsigned pf[4];
            ldsm_x4(paddr + kk2 * 32, pf[0], pf[1], pf[2], pf[3]);
#pragma unroll
            for (int ntp = 0; ntp < 8; ntp++) {
                unsigned r0, r1, r2, r3;
                ldsm_x4(vbase + ntp * (16 * VT_PITCH) + kk2 * 32, r0, r1, r2, r3);
                mma_f16(oacc[2 * ntp],     pf, r0, r1);
                mma_f16(oacc[2 * ntp + 1], pf, r2, r3);
            }
        }
        __syncthreads();
    }

    float inv1 = 1.0f / l1, inv2 = 1.0f / l2;
    int b = bh >> 4, h = bh & 15;
    int row1 = q0 + wq * 16 + (lane >> 2);
#pragma unroll
    for (int nt = 0; nt < 16; nt++) {
        int d = nt * 8 + (lane & 3) * 2;
        __half* p0 = g_y + (size_t)(b * SEQ + row1) * CDIM + h * HD + d;
        __half* p1 = g_y + (size_t)(b * SEQ + row1 + 8) * CDIM + h * HD + d;
        *(__half2*)p0 = __floats2half2_rn(oacc[nt][0] * inv1, oacc[nt][1] * inv1);
        *(__half2*)p1 = __floats2half2_rn(oacc[nt][2] * inv2, oacc[nt][3] * inv2);
    }
}

// ---------------------------------------------------------------------------
extern "C" void kernel_launch(void* const* d_in, const int* in_sizes, int n_in,
                              void* d_out, int out_size)
{
    (void)in_sizes; (void)n_in; (void)out_size;
    const float* x    = (const float*)d_in[0];
    const float* Wqkv = (const float*)d_in[1];
    const float* Wout = (const float*)d_in[2];
    float* out = (float*)d_out;

    __half *y_p, *xh_p, *w1_p, *w2_p;
    cudaGetSymbolAddress((void**)&y_p,  g_y);
    cudaGetSymbolAddress((void**)&xh_p, g_xh);
    cudaGetSymbolAddress((void**)&w1_p, g_w1);
    cudaGetSymbolAddress((void**)&w2_p, g_w2);

    cudaFuncSetAttribute(gemm_f16mma,
                         cudaFuncAttributeMaxDynamicSharedMemorySize, GEMM_SMEM);
    cudaFuncSetAttribute(gemm_qkv_fused,
                         cudaFuncAttributeMaxDynamicSharedMemorySize, GEMM_SMEM);
    cudaFuncSetAttribute(fattn_kernel,
                         cudaFuncAttributeMaxDynamicSharedMemorySize, ATTN_SMEM);

    // 0) fp32 -> fp16 GEMM inputs (single launch)
    tohalf_all_kernel<<<2368, 256>>>(
        (const float4*)x,    (__half2*)xh_p, MTOK * CDIM / 4,
        (const float4*)Wqkv, (__half2*)w1_p, F3 * CDIM / 4,
        (const float4*)Wout, (__half2*)w2_p, CDIM * CDIM / 4);

    // 1) qkv GEMM with fused RoPE/split/scale/V-transpose
    gemm_qkv_fused<<<dim3(F3 / BN, MTOK / BM), 256, GEMM_SMEM>>>(xh_p, w1_p);

    // 2) flash attention (fp16 mma) -> y
    fattn_kernel<<<dim3(SEQ / 64, BATCH * NH), 128, ATTN_SMEM>>>();

    // 3) out = y @ Wout^T  (fp32 output)
    gemm_f16mma<<<dim3(CDIM / BN, MTOK / BM), 256, GEMM_SMEM>>>(y_p, w2_p, out, CDIM, CDIM);
}

// round 15
// speedup vs baseline: 1.1082x; 1.0052x over previous
#include <cuda_runtime.h>
#include <cuda_fp16.h>
#include <math.h>

#define BATCH 8
#define SEQ   512
#define CDIM  2048
#define NH    16
#define HD    128
#define MTOK  (BATCH*SEQ)      // 4096
#define F3    (3*CDIM)         // 6144

// Scratch (static device arrays; no allocation anywhere)
__device__ __half g_q [BATCH*NH*SEQ*HD];    // [bh][t][d] scaled fp16 (rope'd)
__device__ __half g_k [BATCH*NH*SEQ*HD];    // [bh][t][d] fp16 (rope'd)
__device__ __half g_vT[BATCH*NH*HD*SEQ];    // [bh][d][t] fp16 (transposed)
__device__ __half g_y [MTOK * CDIM];        // [b,t,C] fp16
__device__ __half g_xh[MTOK * CDIM];        // fp16 x
__device__ __half g_w1[F3 * CDIM];          // fp16 Wqkv
__device__ __half g_w2[CDIM * CDIM];        // fp16 Wout

// ---------------------------------------------------------------------------
__device__ __forceinline__ unsigned smem_u32(const void* p) {
    unsigned a;
    asm("{ .reg .u64 t; cvta.to.shared.u64 t, %1; cvt.u32.u64 %0, t; }"
        : "=r"(a) : "l"(p));
    return a;
}
__device__ __forceinline__ void cp16(unsigned saddr, const void* gaddr) {
    asm volatile("cp.async.cg.shared.global [%0], [%1], 16;"
                 :: "r"(saddr), "l"(gaddr));
}
__device__ __forceinline__ void ldsm_x4(unsigned addr, unsigned& r0, unsigned& r1,
                                        unsigned& r2, unsigned& r3) {
    asm volatile("ldmatrix.sync.aligned.m8n8.x4.shared.b16 {%0,%1,%2,%3}, [%4];"
                 : "=r"(r0), "=r"(r1), "=r"(r2), "=r"(r3) : "r"(addr));
}
__device__ __forceinline__ void mma_f16(float* c, const unsigned* a,
                                        unsigned b0, unsigned b1) {
    asm volatile(
        "mma.sync.aligned.m16n8k16.row.col.f32.f16.f16.f32 "
        "{%0,%1,%2,%3}, {%4,%5,%6,%7}, {%8,%9}, {%0,%1,%2,%3};"
        : "+f"(c[0]), "+f"(c[1]), "+f"(c[2]), "+f"(c[3])
        : "r"(a[0]), "r"(a[1]), "r"(a[2]), "r"(a[3]), "r"(b0), "r"(b1));
}

// fp32 -> fp16 conversion of all three GEMM inputs, one launch
__global__ __launch_bounds__(256) void tohalf_all_kernel(
    const float4* __restrict__ s0, __half2* __restrict__ d0, int n0,
    const float4* __restrict__ s1, __half2* __restrict__ d1, int n1,
    const float4* __restrict__ s2, __half2* __restrict__ d2, int n2)
{
    const int stride = gridDim.x * blockDim.x;
    const int t0 = blockIdx.x * blockDim.x + threadIdx.x;
    for (int i = t0; i < n0; i += stride) {
        float4 v = s0[i];
        d0[2 * i]     = __floats2half2_rn(v.x, v.y);
        d0[2 * i + 1] = __floats2half2_rn(v.z, v.w);
    }
    for (int i = t0; i < n1; i += stride) {
        float4 v = s1[i];
        d1[2 * i]     = __floats2half2_rn(v.x, v.y);
        d1[2 * i + 1] = __floats2half2_rn(v.z, v.w);
    }
    for (int i = t0; i < n2; i += stride) {
        float4 v = s2[i];
        d2[2 * i]     = __floats2half2_rn(v.x, v.y);
        d2[2 * i + 1] = __floats2half2_rn(v.z, v.w);
    }
}

// ===========================================================================
// fp16 mma.sync GEMM mainloop: 128x128x64 CTA tile, 256 threads = 8 warps
// (2x4 grid, 64x32 warp tiles), 3-stage smem, one barrier per kt.
// (At the legacy-HMMA datapath ceiling — do not touch.)
// ===========================================================================
#define BM 128
#define BN 128
#define BK 64
#define PITCH 144
#define TILE_B (BM * PITCH)
#define STAGE_B (2 * TILE_B)
#define GEMM_SMEM (3 * STAGE_B)             // 110592 B; 2 CTAs = 216 KB

__device__ __forceinline__ void gemm_mainloop(
    const __half* __restrict__ A, const __half* __restrict__ B,
    int Kd, int m0, int n0, unsigned sbase, int tid, float acc[4][4][4])
{
    const int lane = tid & 31;
    const int wid  = tid >> 5;
    const int warpM = wid >> 2;
    const int warpN = wid & 3;

    const int row_ld = tid >> 3;
    const int chk    = tid & 7;

    const int KT = Kd / BK;
    const __half* Aptr = A + (size_t)(m0 + row_ld) * Kd + chk * 8;
    const __half* Bptr = B + (size_t)(n0 + row_ld) * Kd + chk * 8;
    const size_t rstep = (size_t)32 * Kd;
    const unsigned ld_off = (unsigned)(row_ld * PITCH + chk * 16);

#pragma unroll
    for (int pk = 0; pk < 2; pk++) {
        unsigned sA = sbase + pk * STAGE_B + ld_off;
        unsigned sB = sA + TILE_B;
        const __half* ap = Aptr + pk * BK;
        const __half* bp = Bptr + pk * BK;
#pragma unroll
        for (int i = 0; i < 4; i++) {
            cp16(sA + i * (32 * PITCH), ap + i * rstep);
            cp16(sB + i * (32 * PITCH), bp + i * rstep);
        }
        asm volatile("cp.async.commit_group;" ::: "memory");
    }

    const unsigned aRowOff = (unsigned)((warpM * 64 + (lane & 15)) * PITCH
                                        + (lane >> 4) * 16);
    const unsigned bRowOff = (unsigned)((warpN * 32 + (lane & 7)
                                         + ((lane >> 4) * 8)) * PITCH
                                        + ((lane >> 3) & 1) * 16);

    int pf_st = 2;
    int cs_st = 0;

    for (int kt = 0; kt < KT; kt++) {
        if (kt < KT - 2)
            asm volatile("cp.async.wait_group 1;" ::: "memory");
        else
            asm volatile("cp.async.wait_group 0;" ::: "memory");
        __syncthreads();

        if (kt + 2 < KT) {
            unsigned sA = sbase + pf_st * STAGE_B + ld_off;
            unsigned sB = sA + TILE_B;
            const __half* ap = Aptr + (kt + 2) * BK;
            const __half* bp = Bptr + (kt + 2) * BK;
#pragma unroll
            for (int i = 0; i < 4; i++) {
                cp16(sA + i * (32 * PITCH), ap + i * rstep);
                cp16(sB + i * (32 * PITCH), bp + i * rstep);
            }
            asm volatile("cp.async.commit_group;" ::: "memory");
        }
        if (++pf_st == 3) pf_st = 0;

        const unsigned aBase = sbase + cs_st * STAGE_B + aRowOff;
        const unsigned bBase = sbase + cs_st * STAGE_B + TILE_B + bRowOff;
        if (++cs_st == 3) cs_st = 0;

#pragma unroll
        for (int kk = 0; kk < 4; kk++) {
            unsigned af[4][4];
#pragma unroll
            for (int mt = 0; mt < 4; mt++)
                ldsm_x4(aBase + mt * (16 * PITCH) + kk * 32,
                        af[mt][0], af[mt][1], af[mt][2], af[mt][3]);
            unsigned bf[4][2];
#pragma unroll
            for (int ntp = 0; ntp < 2; ntp++) {
                unsigned r0, r1, r2, r3;
                ldsm_x4(bBase + ntp * (16 * PITCH) + kk * 32, r0, r1, r2, r3);
                bf[2 * ntp][0] = r0;     bf[2 * ntp][1] = r1;
                bf[2 * ntp + 1][0] = r2; bf[2 * ntp + 1][1] = r3;
            }
#pragma unroll
            for (int mt = 0; mt < 4; mt++)
#pragma unroll
                for (int nt = 0; nt < 4; nt++)
                    mma_f16(acc[mt][nt], af[mt], bf[nt][0], bf[nt][1]);
        }
    }
}

// ---------------------------------------------------------------------------
// Generic GEMM with fp32 output (output projection)
// ---------------------------------------------------------------------------
__global__ __launch_bounds__(256, 2) void gemm_f16mma(
    const __half* __restrict__ A, const __half* __restrict__ B,
    float* __restrict__ C, int Nd, int Kd)
{
    extern __shared__ char smem[];
    const unsigned sbase = smem_u32(smem);
    const int tid  = threadIdx.x;
    const int lane = tid & 31;
    const int wid  = tid >> 5;
    const int m0 = blockIdx.y * BM;
    const int n0 = blockIdx.x * BN;

    float acc[4][4][4];
#pragma unroll
    for (int a = 0; a < 4; a++)
#pragma unroll
        for (int b = 0; b < 4; b++)
#pragma unroll
            for (int c = 0; c < 4; c++) acc[a][b][c] = 0.0f;

    gemm_mainloop(A, B, Kd, m0, n0, sbase, tid, acc);

    const int rBase = m0 + (wid >> 2) * 64 + (lane >> 2);
    const int cBase = n0 + (wid & 3) * 32 + (lane & 3) * 2;
#pragma unroll
    for (int mt = 0; mt < 4; mt++)
#pragma unroll
        for (int nt = 0; nt < 4; nt++) {
            float* p0 = C + (size_t)(rBase + mt * 16) * Nd + cBase + nt * 8;
            float* p1 = C + (size_t)(rBase + mt * 16 + 8) * Nd + cBase + nt * 8;
            *(float2*)p0 = make_float2(acc[mt][nt][0], acc[mt][nt][1]);
            *(float2*)p1 = make_float2(acc[mt][nt][2], acc[mt][nt][3]);
        }
}

// ---------------------------------------------------------------------------
// QKV GEMM with fused RoPE + split + scale + V-transpose epilogue.
// ---------------------------------------------------------------------------
#define VT_SP 136     // smem transpose pitch in halves (128 + 8)

__global__ __launch_bounds__(256, 2) void gemm_qkv_fused(
    const __half* __restrict__ A, const __half* __restrict__ B)
{
    extern __shared__ char smem[];
    const unsigned sbase = smem_u32(smem);
    const int tid  = threadIdx.x;
    const int lane = tid & 31;
    const int wid  = tid >> 5;
    const int warpM = wid >> 2;
    const int warpN = wid & 3;
    const int m0 = blockIdx.y * BM;
    const int n0 = blockIdx.x * BN;

    float acc[4][4][4];
#pragma unroll
    for (int a = 0; a < 4; a++)
#pragma unroll
        for (int b = 0; b < 4; b++)
#pragma unroll
            for (int c = 0; c < 4; c++) acc[a][b][c] = 0.0f;

    gemm_mainloop(A, B, CDIM, m0, n0, sbase, tid, acc);

    const int kind = n0 >> 11;               // 0=q 1=k 2=v
    const int h    = (n0 & 2047) >> 7;
    const int rBase = m0 + warpM * 64 + (lane >> 2);
    const int cLoc  = warpN * 32 + (lane & 3) * 2;

    if (kind < 2) {
        if (warpN == 0) {
            const int dlo = (lane & 3) * 2;
#pragma unroll
            for (int j = 0; j < 2; j++) {
                float fr = __powf(10000.0f, -(float)(dlo + j) * 0.125f);
#pragma unroll
                for (int mt = 0; mt < 4; mt++) {
                    int t0 = (rBase + mt * 16) & (SEQ - 1);
                    float s0, c0, s1, c1;
                    __sincosf((float)t0 * fr, &s0, &c0);
                    __sincosf((float)(t0 + 8) * fr, &s1, &c1);
                    float lo0 = acc[mt][0][j],     hi0 = acc[mt][1][j];
                    acc[mt][0][j]     = lo0 * c0 - hi0 * s0;
                    acc[mt][1][j]     = hi0 * c0 + lo0 * s0;
                    float lo1 = acc[mt][0][2 + j], hi1 = acc[mt][1][2 + j];
                    acc[mt][0][2 + j] = lo1 * c1 - hi1 * s1;
                    acc[mt][1][2 + j] = hi1 * c1 + lo1 * s1;
                }
            }
        }
        const float scale = (kind == 0) ? 0.08838834764831845f : 1.0f;
        __half* dst = (kind == 0) ? g_q : g_k;
#pragma unroll
        for (int mt = 0; mt < 4; mt++) {
            int r0 = rBase + mt * 16;
            int b0 = r0 >> 9, t0 = r0 & (SEQ - 1);
            size_t base = ((size_t)(b0 * NH + h) * SEQ + t0) * HD;
#pragma unroll
            for (int nt = 0; nt < 4; nt++) {
                int d = cLoc + nt * 8;
                *(__half2*)(dst + base + d) =
                    __floats2half2_rn(acc[mt][nt][0] * scale,
                                      acc[mt][nt][1] * scale);
                *(__half2*)(dst + base + 8 * HD + d) =
                    __floats2half2_rn(acc[mt][nt][2] * scale,
                                      acc[mt][nt][3] * scale);
            }
        }
    } else {
        __syncthreads();
        __half* vs = (__half*)smem;
        const int tLoc = (rBase - m0);
#pragma unroll
        for (int mt = 0; mt < 4; mt++) {
            int tl = tLoc + mt * 16;
#pragma unroll
            for (int nt = 0; nt < 4; nt++) {
                int d = cLoc + nt * 8;
                vs[d * VT_SP + tl]           = __float2half_rn(acc[mt][nt][0]);
                vs[(d + 1) * VT_SP + tl]     = __float2half_rn(acc[mt][nt][1]);
                vs[d * VT_SP + tl + 8]       = __float2half_rn(acc[mt][nt][2]);
                vs[(d + 1) * VT_SP + tl + 8] = __float2half_rn(acc[mt][nt][3]);
            }
        }
        __syncthreads();
        const int b = m0 >> 9, t0g = m0 & (SEQ - 1);
        __half* vbase = g_vT + ((size_t)(b * NH + h) * HD) * SEQ + t0g;
#pragma unroll
        for (int i = 0; i < 8; i++) {
            int id = tid + i * 256;
            int dr = id >> 4, ch = id & 15;
            *(uint4*)(vbase + (size_t)dr * SEQ + ch * 8) =
                *(uint4*)(vs + dr * VT_SP + ch * 8);
        }
    }
}

// ===========================================================================
// Flash attention, fp16 mma: CTA = 64 queries x 1 (b,h), Bc=64 keys.
// Softmax/rescale/P-store/barriers once per 64 keys (halved overhead).
// Q 64x128h (272B pitch), K 64x128h x2, V^T 128x64h (144B pitch) x2,
// P 64x64h (144B pitch).  SMEM 96 KB -> 2 CTAs/SM.
// ===========================================================================
#define QK_PITCH 272
#define VT_PITCH 144
#define P_PITCH  144
#define OFF_Q    0
#define OFF_K0   17408
#define OFF_K1   34816
#define OFF_V0   52224
#define OFF_V1   70656
#define OFF_P    89088
#define ATTN_SMEM 98304

__global__ __launch_bounds__(128, 2) void fattn_kernel()
{
    extern __shared__ char smem[];
    const unsigned sb = smem_u32(smem);
    const int bh = blockIdx.y;
    const int qt = blockIdx.x;
    const int q0 = qt * 64;
    const int jmax = qt;                    // 64-key tiles 0..qt
    const int tid = threadIdx.x;
    const int lane = tid & 31;
    const int wq = tid >> 5;

    // ---- stage Q tile (64 x 128 halves) and extract fragments
    {
        const __half* qg = g_q + ((size_t)bh * SEQ + q0) * HD;
#pragma unroll
        for (int i = 0; i < 8; i++) {
            int id = tid + i * 128;
            int row = id >> 4, c16 = id & 15;
            cp16(sb + OFF_Q + row * QK_PITCH + c16 * 16, qg + row * HD + c16 * 8);
        }
        asm volatile("cp.async.commit_group;" ::: "memory");
        asm volatile("cp.async.wait_group 0;" ::: "memory");
        __syncthreads();
    }
    unsigned qf[8][4];
    {
        unsigned qaddr = sb + OFF_Q + (wq * 16 + (lane & 15)) * QK_PITCH
                       + (lane >> 4) * 16;
#pragma unroll
        for (int kk = 0; kk < 8; kk++)
            ldsm_x4(qaddr + kk * 32, qf[kk][0], qf[kk][1], qf[kk][2], qf[kk][3]);
    }
    __syncthreads();

    float m1 = -1e30f, m2 = -1e30f, l1 = 0.0f, l2 = 0.0f;
    float oacc[16][4];
#pragma unroll
    for (int nt = 0; nt < 16; nt++)
#pragma unroll
        for (int c = 0; c < 4; c++) oacc[nt][c] = 0.0f;

    // 64-key tile loader (K [64,128] + V^T [128,64]); one commit group
    auto load_tile = [&](int j) {
        unsigned kb = sb + ((j & 1) ? OFF_K1 : OFF_K0);
        unsigned vb = sb + ((j & 1) ? OFF_V1 : OFF_V0);
        const __half* kg = g_k + ((size_t)bh * SEQ + j * 64) * HD;
        const __half* vg = g_vT + (size_t)bh * HD * SEQ + j * 64;
#pragma unroll
        for (int i = 0; i < 8; i++) {
            int id = tid + i * 128;
            int kr = id >> 4, kc = id & 15;
            cp16(kb + kr * QK_PITCH + kc * 16, kg + kr * HD + kc * 8);
            int vr = id >> 3, vc = id & 7;
            cp16(vb + vr * VT_PITCH + vc * 16, vg + (size_t)vr * SEQ + vc * 8);
        }
        asm volatile("cp.async.commit_group;" ::: "memory");
    };

    load_tile(0);

    const int rowg1 = q0 + wq * 16 + (lane >> 2);
    const unsigned bOff = (unsigned)(((lane & 7) + ((lane >> 4) * 8)) * QK_PITCH
                                     + ((lane >> 3) & 1) * 16);
    const unsigned vOff = (unsigned)(((lane & 7) + ((lane >> 4) * 8)) * VT_PITCH
                                     + ((lane >> 3) & 1) * 16);

    for (int j = 0; j <= jmax; j++) {
        asm volatile("cp.async.wait_group 0;" ::: "memory");
        __syncthreads();
        if (j < jmax) load_tile(j + 1);

        // ---- S = Q K^T  (warp: 16 rows x 64 keys)
        float sacc[8][4];
#pragma unroll
        for (int nt = 0; nt < 8; nt++)
#pragma unroll
            for (int c = 0; c < 4; c++) sacc[nt][c] = 0.0f;

        const unsigned kbase = sb + ((j & 1) ? OFF_K1 : OFF_K0) + bOff;
#pragma unroll
        for (int kk = 0; kk < 8; kk++) {
            unsigned bf[8][2];
#pragma unroll
            for (int ntp = 0; ntp < 4; ntp++) {
                unsigned r0, r1, r2, r3;
                ldsm_x4(kbase + ntp * (16 * QK_PITCH) + kk * 32, r0, r1, r2, r3);
                bf[2 * ntp][0] = r0;     bf[2 * ntp][1] = r1;
                bf[2 * ntp + 1][0] = r2; bf[2 * ntp + 1][1] = r3;
            }
#pragma unroll
            for (int nt = 0; nt < 8; nt++)
                mma_f16(sacc[nt], qf[kk], bf[nt][0], bf[nt][1]);
        }

        // ---- causal mask (tile covers keys j*64 .. j*64+63)
        if (j * 64 + 63 > q0 + wq * 16) {
#pragma unroll
            for (int nt = 0; nt < 8; nt++) {
                int colb = j * 64 + nt * 8 + (lane & 3) * 2;
                if (colb     > rowg1)     sacc[nt][0] = -1e30f;
                if (colb + 1 > rowg1)     sacc[nt][1] = -1e30f;
                if (colb     > rowg1 + 8) sacc[nt][2] = -1e30f;
                if (colb + 1 > rowg1 + 8) sacc[nt][3] = -1e30f;
            }
        }

        // ---- online softmax (once per 64 keys)
        float tm1 = -1e30f, tm2 = -1e30f;
#pragma unroll
        for (int nt = 0; nt < 8; nt++) {
            tm1 = fmaxf(tm1, fmaxf(sacc[nt][0], sacc[nt][1]));
            tm2 = fmaxf(tm2, fmaxf(sacc[nt][2], sacc[nt][3]));
        }
        tm1 = fmaxf(tm1, __shfl_xor_sync(0xffffffffu, tm1, 1));
        tm1 = fmaxf(tm1, __shfl_xor_sync(0xffffffffu, tm1, 2));
        tm2 = fmaxf(tm2, __shfl_xor_sync(0xffffffffu, tm2, 1));
        tm2 = fmaxf(tm2, __shfl_xor_sync(0xffffffffu, tm2, 2));

        float m1n = fmaxf(m1, tm1), m2n = fmaxf(m2, tm2);
        float corr1 = __expf(m1 - m1n), corr2 = __expf(m2 - m2n);
        m1 = m1n; m2 = m2n;

        float rs1 = 0.0f, rs2 = 0.0f;
#pragma unroll
        for (int nt = 0; nt < 8; nt++) {
            sacc[nt][0] = __expf(sacc[nt][0] - m1n);
            sacc[nt][1] = __expf(sacc[nt][1] - m1n);
            sacc[nt][2] = __expf(sacc[nt][2] - m2n);
            sacc[nt][3] = __expf(sacc[nt][3] - m2n);
            rs1 += sacc[nt][0] + sacc[nt][1];
            rs2 += sacc[nt][2] + sacc[nt][3];
        }
        rs1 += __shfl_xor_sync(0xffffffffu, rs1, 1);
        rs1 += __shfl_xor_sync(0xffffffffu, rs1, 2);
        rs2 += __shfl_xor_sync(0xffffffffu, rs2, 1);
        rs2 += __shfl_xor_sync(0xffffffffu, rs2, 2);
        l1 = l1 * corr1 + rs1;
        l2 = l2 * corr2 + rs2;

#pragma unroll
        for (int nt = 0; nt < 16; nt++) {
            oacc[nt][0] *= corr1; oacc[nt][1] *= corr1;
            oacc[nt][2] *= corr2; oacc[nt][3] *= corr2;
        }

        // ---- P -> smem (fp16), 64x64
        {
            int pr1 = wq * 16 + (lane >> 2);
            int pc = (lane & 3) * 2;
#pragma unroll
            for (int nt = 0; nt < 8; nt++) {
                *(__half2*)(smem + OFF_P + pr1 * P_PITCH + (nt * 8 + pc) * 2) =
                    __floats2half2_rn(sacc[nt][0], sacc[nt][1]);
                *(__half2*)(smem + OFF_P + (pr1 + 8) * P_PITCH + (nt * 8 + pc) * 2) =
                    __floats2half2_rn(sacc[nt][2], sacc[nt][3]);
            }
        }
        __syncthreads();

        // ---- O += P V   (4 k16 steps over 64 keys)
        const unsigned vbase = sb + ((j & 1) ? OFF_V1 : OFF_V0) + vOff;
        const unsigned paddr = sb + OFF_P + (wq * 16 + (lane & 15)) * P_PITCH
                             + (lane >> 4) * 16;
#pragma unroll
        for (int kk2 = 0; kk2 < 4; kk2++) {
            unsigned pf[4];
            ldsm_x4(paddr + kk2 * 32, pf[0], pf[1], pf[2], pf[3]);
#pragma unroll
            for (int ntp = 0; ntp < 8; ntp++) {
                unsigned r0, r1, r2, r3;
                ldsm_x4(vbase + ntp * (16 * VT_PITCH) + kk2 * 32, r0, r1, r2, r3);
                mma_f16(oacc[2 * ntp],     pf, r0, r1);
                mma_f16(oacc[2 * ntp + 1], pf, r2, r3);
            }
        }
        // no bottom barrier: next iteration's top barrier orders P/V reuse
    }

    float inv1 = 1.0f / l1, inv2 = 1.0f / l2;
    int b = bh >> 4, h = bh & 15;
    int row1 = q0 + wq * 16 + (lane >> 2);
#pragma unroll
    for (int nt = 0; nt < 16; nt++) {
        int d = nt * 8 + (lane & 3) * 2;
        __half* p0 = g_y + (size_t)(b * SEQ + row1) * CDIM + h * HD + d;
        __half* p1 = g_y + (size_t)(b * SEQ + row1 + 8) * CDIM + h * HD + d;
        *(__half2*)p0 = __floats2half2_rn(oacc[nt][0] * inv1, oacc[nt][1] * inv1);
        *(__half2*)p1 = __floats2half2_rn(oacc[nt][2] * inv2, oacc[nt][3] * inv2);
    }
}

// ---------------------------------------------------------------------------
extern "C" void kernel_launch(void* const* d_in, const int* in_sizes, int n_in,
                              void* d_out, int out_size)
{
    (void)in_sizes; (void)n_in; (void)out_size;
    const float* x    = (const float*)d_in[0];
    const float* Wqkv = (const float*)d_in[1];
    const float* Wout = (const float*)d_in[2];
    float* out = (float*)d_out;

    __half *y_p, *xh_p, *w1_p, *w2_p;
    cudaGetSymbolAddress((void**)&y_p,  g_y);
    cudaGetSymbolAddress((void**)&xh_p, g_xh);
    cudaGetSymbolAddress((void**)&w1_p, g_w1);
    cudaGetSymbolAddress((void**)&w2_p, g_w2);

    cudaFuncSetAttribute(gemm_f16mma,
                         cudaFuncAttributeMaxDynamicSharedMemorySize, GEMM_SMEM);
    cudaFuncSetAttribute(gemm_qkv_fused,
                         cudaFuncAttributeMaxDynamicSharedMemorySize, GEMM_SMEM);
    cudaFuncSetAttribute(fattn_kernel,
                         cudaFuncAttributeMaxDynamicSharedMemorySize, ATTN_SMEM);

    // 0) fp32 -> fp16 GEMM inputs (single launch)
    tohalf_all_kernel<<<2368, 256>>>(
        (const float4*)x,    (__half2*)xh_p, MTOK * CDIM / 4,
        (const float4*)Wqkv, (__half2*)w1_p, F3 * CDIM / 4,
        (const float4*)Wout, (__half2*)w2_p, CDIM * CDIM / 4);

    // 1) qkv GEMM with fused RoPE/split/scale/V-transpose
    gemm_qkv_fused<<<dim3(F3 / BN, MTOK / BM), 256, GEMM_SMEM>>>(xh_p, w1_p);

    // 2) flash attention (fp16 mma, Bc=64) -> y
    fattn_kernel<<<dim3(SEQ / 64, BATCH * NH), 128, ATTN_SMEM>>>();

    // 3) out = y @ Wout^T  (fp32 output)
    gemm_f16mma<<<dim3(CDIM / BN, MTOK / BM), 256, GEMM_SMEM>>>(y_p, w2_p, out, CDIM, CDIM);
}

// round 16
// speedup vs baseline: 1.1210x; 1.0116x over previous
#include <cuda_runtime.h>
#include <cuda_fp16.h>
#include <math.h>

#define BATCH 8
#define SEQ   512
#define CDIM  2048
#define NH    16
#define HD    128
#define MTOK  (BATCH*SEQ)      // 4096
#define F3    (3*CDIM)         // 6144

// Scratch (static device arrays; no allocation anywhere)
__device__ __half g_q [BATCH*NH*SEQ*HD];    // [bh][t][d] scaled fp16 (rope'd)
__device__ __half g_k [BATCH*NH*SEQ*HD];    // [bh][t][d] fp16 (rope'd)
__device__ __half g_vT[BATCH*NH*HD*SEQ];    // [bh][d][t] fp16 (transposed)
__device__ __half g_y [MTOK * CDIM];        // [b,t,C] fp16
__device__ __half g_xh[MTOK * CDIM];        // fp16 x
__device__ __half g_w1[F3 * CDIM];          // fp16 Wqkv
__device__ __half g_w2[CDIM * CDIM];        // fp16 Wout

// ---------------------------------------------------------------------------
__device__ __forceinline__ unsigned smem_u32(const void* p) {
    unsigned a;
    asm("{ .reg .u64 t; cvta.to.shared.u64 t, %1; cvt.u32.u64 %0, t; }"
        : "=r"(a) : "l"(p));
    return a;
}
__device__ __forceinline__ void cp16(unsigned saddr, const void* gaddr) {
    asm volatile("cp.async.cg.shared.global [%0], [%1], 16;"
                 :: "r"(saddr), "l"(gaddr));
}
__device__ __forceinline__ void ldsm_x4(unsigned addr, unsigned& r0, unsigned& r1,
                                        unsigned& r2, unsigned& r3) {
    asm volatile("ldmatrix.sync.aligned.m8n8.x4.shared.b16 {%0,%1,%2,%3}, [%4];"
                 : "=r"(r0), "=r"(r1), "=r"(r2), "=r"(r3) : "r"(addr));
}
__device__ __forceinline__ void mma_f16(float* c, const unsigned* a,
                                        unsigned b0, unsigned b1) {
    asm volatile(
        "mma.sync.aligned.m16n8k16.row.col.f32.f16.f16.f32 "
        "{%0,%1,%2,%3}, {%4,%5,%6,%7}, {%8,%9}, {%0,%1,%2,%3};"
        : "+f"(c[0]), "+f"(c[1]), "+f"(c[2]), "+f"(c[3])
        : "r"(a[0]), "r"(a[1]), "r"(a[2]), "r"(a[3]), "r"(b0), "r"(b1));
}

// fp32 -> fp16 conversion of x and Wqkv (w2 handled inside the QKV launch)
__global__ __launch_bounds__(256) void tohalf_all_kernel(
    const float4* __restrict__ s0, __half2* __restrict__ d0, int n0,
    const float4* __restrict__ s1, __half2* __restrict__ d1, int n1)
{
    const int stride = gridDim.x * blockDim.x;
    const int t0 = blockIdx.x * blockDim.x + threadIdx.x;
    for (int i = t0; i < n0; i += stride) {
        float4 v = s0[i];
        d0[2 * i]     = __floats2half2_rn(v.x, v.y);
        d0[2 * i + 1] = __floats2half2_rn(v.z, v.w);
    }
    for (int i = t0; i < n1; i += stride) {
        float4 v = s1[i];
        d1[2 * i]     = __floats2half2_rn(v.x, v.y);
        d1[2 * i + 1] = __floats2half2_rn(v.z, v.w);
    }
}

// ===========================================================================
// fp16 mma.sync GEMM mainloop: 128x128x64 CTA tile, 256 threads = 8 warps
// (2x4 grid, 64x32 warp tiles), 3-stage smem, one barrier per kt.
// (At the legacy-HMMA datapath ceiling — do not touch.)
// ===========================================================================
#define BM 128
#define BN 128
#define BK 64
#define PITCH 144
#define TILE_B (BM * PITCH)
#define STAGE_B (2 * TILE_B)
#define GEMM_SMEM (3 * STAGE_B)             // 110592 B; 2 CTAs = 216 KB

__device__ __forceinline__ void gemm_mainloop(
    const __half* __restrict__ A, const __half* __restrict__ B,
    int Kd, int m0, int n0, unsigned sbase, int tid, float acc[4][4][4])
{
    const int lane = tid & 31;
    const int wid  = tid >> 5;
    const int warpM = wid >> 2;
    const int warpN = wid & 3;

    const int row_ld = tid >> 3;
    const int chk    = tid & 7;

    const int KT = Kd / BK;
    const __half* Aptr = A + (size_t)(m0 + row_ld) * Kd + chk * 8;
    const __half* Bptr = B + (size_t)(n0 + row_ld) * Kd + chk * 8;
    const size_t rstep = (size_t)32 * Kd;
    const unsigned ld_off = (unsigned)(row_ld * PITCH + chk * 16);

#pragma unroll
    for (int pk = 0; pk < 2; pk++) {
        unsigned sA = sbase + pk * STAGE_B + ld_off;
        unsigned sB = sA + TILE_B;
        const __half* ap = Aptr + pk * BK;
        const __half* bp = Bptr + pk * BK;
#pragma unroll
        for (int i = 0; i < 4; i++) {
            cp16(sA + i * (32 * PITCH), ap + i * rstep);
            cp16(sB + i * (32 * PITCH), bp + i * rstep);
        }
        asm volatile("cp.async.commit_group;" ::: "memory");
    }

    const unsigned aRowOff = (unsigned)((warpM * 64 + (lane & 15)) * PITCH
                                        + (lane >> 4) * 16);
    const unsigned bRowOff = (unsigned)((warpN * 32 + (lane & 7)
                                         + ((lane >> 4) * 8)) * PITCH
                                        + ((lane >> 3) & 1) * 16);

    int pf_st = 2;
    int cs_st = 0;

    for (int kt = 0; kt < KT; kt++) {
        if (kt < KT - 2)
            asm volatile("cp.async.wait_group 1;" ::: "memory");
        else
            asm volatile("cp.async.wait_group 0;" ::: "memory");
        __syncthreads();

        if (kt + 2 < KT) {
            unsigned sA = sbase + pf_st * STAGE_B + ld_off;
            unsigned sB = sA + TILE_B;
            const __half* ap = Aptr + (kt + 2) * BK;
            const __half* bp = Bptr + (kt + 2) * BK;
#pragma unroll
            for (int i = 0; i < 4; i++) {
                cp16(sA + i * (32 * PITCH), ap + i * rstep);
                cp16(sB + i * (32 * PITCH), bp + i * rstep);
            }
            asm volatile("cp.async.commit_group;" ::: "memory");
        }
        if (++pf_st == 3) pf_st = 0;

        const unsigned aBase = sbase + cs_st * STAGE_B + aRowOff;
        const unsigned bBase = sbase + cs_st * STAGE_B + TILE_B + bRowOff;
        if (++cs_st == 3) cs_st = 0;

#pragma unroll
        for (int kk = 0; kk < 4; kk++) {
            unsigned af[4][4];
#pragma unroll
            for (int mt = 0; mt < 4; mt++)
                ldsm_x4(aBase + mt * (16 * PITCH) + kk * 32,
                        af[mt][0], af[mt][1], af[mt][2], af[mt][3]);
            unsigned bf[4][2];
#pragma unroll
            for (int ntp = 0; ntp < 2; ntp++) {
                unsigned r0, r1, r2, r3;
                ldsm_x4(bBase + ntp * (16 * PITCH) + kk * 32, r0, r1, r2, r3);
                bf[2 * ntp][0] = r0;     bf[2 * ntp][1] = r1;
                bf[2 * ntp + 1][0] = r2; bf[2 * ntp + 1][1] = r3;
            }
#pragma unroll
            for (int mt = 0; mt < 4; mt++)
#pragma unroll
                for (int nt = 0; nt < 4; nt++)
                    mma_f16(acc[mt][nt], af[mt], bf[nt][0], bf[nt][1]);
        }
    }
}

// ---------------------------------------------------------------------------
// Generic GEMM with fp32 output (output projection)
// ---------------------------------------------------------------------------
__global__ __launch_bounds__(256, 2) void gemm_f16mma(
    const __half* __restrict__ A, const __half* __restrict__ B,
    float* __restrict__ C, int Nd, int Kd)
{
    extern __shared__ char smem[];
    const unsigned sbase = smem_u32(smem);
    const int tid  = threadIdx.x;
    const int lane = tid & 31;
    const int wid  = tid >> 5;
    const int m0 = blockIdx.y * BM;
    const int n0 = blockIdx.x * BN;

    float acc[4][4][4];
#pragma unroll
    for (int a = 0; a < 4; a++)
#pragma unroll
        for (int b = 0; b < 4; b++)
#pragma unroll
            for (int c = 0; c < 4; c++) acc[a][b][c] = 0.0f;

    gemm_mainloop(A, B, Kd, m0, n0, sbase, tid, acc);

    const int rBase = m0 + (wid >> 2) * 64 + (lane >> 2);
    const int cBase = n0 + (wid & 3) * 32 + (lane & 3) * 2;
#pragma unroll
    for (int mt = 0; mt < 4; mt++)
#pragma unroll
        for (int nt = 0; nt < 4; nt++) {
            float* p0 = C + (size_t)(rBase + mt * 16) * Nd + cBase + nt * 8;
            float* p1 = C + (size_t)(rBase + mt * 16 + 8) * Nd + cBase + nt * 8;
            *(float2*)p0 = make_float2(acc[mt][nt][0], acc[mt][nt][1]);
            *(float2*)p1 = make_float2(acc[mt][nt][2], acc[mt][nt][3]);
        }
}

// ---------------------------------------------------------------------------
// QKV GEMM with fused RoPE + split + scale + V-transpose epilogue.
// Extra grid slice (blockIdx.y == 32): fp32->fp16 conversion of Wout,
// riding in the QKV launch's partial last wave (w2 only needed later).
// ---------------------------------------------------------------------------
#define VT_SP 136     // smem transpose pitch in halves (128 + 8)

__global__ __launch_bounds__(256, 2) void gemm_qkv_fused(
    const __half* __restrict__ A, const __half* __restrict__ B,
    const float4* __restrict__ w2src, __half2* __restrict__ w2dst)
{
    // ---- w2 conversion slice
    if (blockIdx.y == 32) {
        const int n4 = CDIM * CDIM / 4;                 // 1M float4s
        const int stride = 48 * 256;
        for (int i = blockIdx.x * 256 + threadIdx.x; i < n4; i += stride) {
            float4 v = w2src[i];
            w2dst[2 * i]     = __floats2half2_rn(v.x, v.y);
            w2dst[2 * i + 1] = __floats2half2_rn(v.z, v.w);
        }
        return;
    }

    extern __shared__ char smem[];
    const unsigned sbase = smem_u32(smem);
    const int tid  = threadIdx.x;
    const int lane = tid & 31;
    const int wid  = tid >> 5;
    const int warpM = wid >> 2;
    const int warpN = wid & 3;
    const int m0 = blockIdx.y * BM;
    const int n0 = blockIdx.x * BN;

    float acc[4][4][4];
#pragma unroll
    for (int a = 0; a < 4; a++)
#pragma unroll
        for (int b = 0; b < 4; b++)
#pragma unroll
            for (int c = 0; c < 4; c++) acc[a][b][c] = 0.0f;

    gemm_mainloop(A, B, CDIM, m0, n0, sbase, tid, acc);

    const int kind = n0 >> 11;               // 0=q 1=k 2=v
    const int h    = (n0 & 2047) >> 7;
    const int rBase = m0 + warpM * 64 + (lane >> 2);
    const int cLoc  = warpN * 32 + (lane & 3) * 2;

    if (kind < 2) {
        if (warpN == 0) {
            const int dlo = (lane & 3) * 2;
#pragma unroll
            for (int j = 0; j < 2; j++) {
                float fr = __powf(10000.0f, -(float)(dlo + j) * 0.125f);
#pragma unroll
                for (int mt = 0; mt < 4; mt++) {
                    int t0 = (rBase + mt * 16) & (SEQ - 1);
                    float s0, c0, s1, c1;
                    __sincosf((float)t0 * fr, &s0, &c0);
                    __sincosf((float)(t0 + 8) * fr, &s1, &c1);
                    float lo0 = acc[mt][0][j],     hi0 = acc[mt][1][j];
                    acc[mt][0][j]     = lo0 * c0 - hi0 * s0;
                    acc[mt][1][j]     = hi0 * c0 + lo0 * s0;
                    float lo1 = acc[mt][0][2 + j], hi1 = acc[mt][1][2 + j];
                    acc[mt][0][2 + j] = lo1 * c1 - hi1 * s1;
                    acc[mt][1][2 + j] = hi1 * c1 + lo1 * s1;
                }
            }
        }
        const float scale = (kind == 0) ? 0.08838834764831845f : 1.0f;
        __half* dst = (kind == 0) ? g_q : g_k;
#pragma unroll
        for (int mt = 0; mt < 4; mt++) {
            int r0 = rBase + mt * 16;
            int b0 = r0 >> 9, t0 = r0 & (SEQ - 1);
            size_t base = ((size_t)(b0 * NH + h) * SEQ + t0) * HD;
#pragma unroll
            for (int nt = 0; nt < 4; nt++) {
                int d = cLoc + nt * 8;
                *(__half2*)(dst + base + d) =
                    __floats2half2_rn(acc[mt][nt][0] * scale,
                                      acc[mt][nt][1] * scale);
                *(__half2*)(dst + base + 8 * HD + d) =
                    __floats2half2_rn(acc[mt][nt][2] * scale,
                                      acc[mt][nt][3] * scale);
            }
        }
    } else {
        __syncthreads();
        __half* vs = (__half*)smem;
        const int tLoc = (rBase - m0);
#pragma unroll
        for (int mt = 0; mt < 4; mt++) {
            int tl = tLoc + mt * 16;
#pragma unroll
            for (int nt = 0; nt < 4; nt++) {
                int d = cLoc + nt * 8;
                vs[d * VT_SP + tl]           = __float2half_rn(acc[mt][nt][0]);
                vs[(d + 1) * VT_SP + tl]     = __float2half_rn(acc[mt][nt][1]);
                vs[d * VT_SP + tl + 8]       = __float2half_rn(acc[mt][nt][2]);
                vs[(d + 1) * VT_SP + tl + 8] = __float2half_rn(acc[mt][nt][3]);
            }
        }
        __syncthreads();
        const int b = m0 >> 9, t0g = m0 & (SEQ - 1);
        __half* vbase = g_vT + ((size_t)(b * NH + h) * HD) * SEQ + t0g;
#pragma unroll
        for (int i = 0; i < 8; i++) {
            int id = tid + i * 256;
            int dr = id >> 4, ch = id & 15;
            *(uint4*)(vbase + (size_t)dr * SEQ + ch * 8) =
                *(uint4*)(vs + dr * VT_SP + ch * 8);
        }
    }
}

// ===========================================================================
// Flash attention, fp16 mma: CTA = 64 queries x 1 (b,h), Bc=64 keys.
// Heavy CTAs (large qt) launch FIRST for wave load balance.
// ===========================================================================
#define QK_PITCH 272
#define VT_PITCH 144
#define P_PITCH  144
#define OFF_Q    0
#define OFF_K0   17408
#define OFF_K1   34816
#define OFF_V0   52224
#define OFF_V1   70656
#define OFF_P    89088
#define ATTN_SMEM 98304

__global__ __launch_bounds__(128, 2) void fattn_kernel()
{
    extern __shared__ char smem[];
    const unsigned sb = smem_u32(smem);
    const int bh = blockIdx.y;
    const int qt = gridDim.x - 1 - blockIdx.x;   // heavy tiles first
    const int q0 = qt * 64;
    const int jmax = qt;
    const int tid = threadIdx.x;
    const int lane = tid & 31;
    const int wq = tid >> 5;

    {
        const __half* qg = g_q + ((size_t)bh * SEQ + q0) * HD;
#pragma unroll
        for (int i = 0; i < 8; i++) {
            int id = tid + i * 128;
            int row = id >> 4, c16 = id & 15;
            cp16(sb + OFF_Q + row * QK_PITCH + c16 * 16, qg + row * HD + c16 * 8);
        }
        asm volatile("cp.async.commit_group;" ::: "memory");
        asm volatile("cp.async.wait_group 0;" ::: "memory");
        __syncthreads();
    }
    unsigned qf[8][4];
    {
        unsigned qaddr = sb + OFF_Q + (wq * 16 + (lane & 15)) * QK_PITCH
                       + (lane >> 4) * 16;
#pragma unroll
        for (int kk = 0; kk < 8; kk++)
            ldsm_x4(qaddr + kk * 32, qf[kk][0], qf[kk][1], qf[kk][2], qf[kk][3]);
    }
    __syncthreads();

    float m1 = -1e30f, m2 = -1e30f, l1 = 0.0f, l2 = 0.0f;
    float oacc[16][4];
#pragma unroll
    for (int nt = 0; nt < 16; nt++)
#pragma unroll
        for (int c = 0; c < 4; c++) oacc[nt][c] = 0.0f;

    auto load_tile = [&](int j) {
        unsigned kb = sb + ((j & 1) ? OFF_K1 : OFF_K0);
        unsigned vb = sb + ((j & 1) ? OFF_V1 : OFF_V0);
        const __half* kg = g_k + ((size_t)bh * SEQ + j * 64) * HD;
        const __half* vg = g_vT + (size_t)bh * HD * SEQ + j * 64;
#pragma unroll
        for (int i = 0; i < 8; i++) {
            int id = tid + i * 128;
            int kr = id >> 4, kc = id & 15;
            cp16(kb + kr * QK_PITCH + kc * 16, kg + kr * HD + kc * 8);
            int vr = id >> 3, vc = id & 7;
            cp16(vb + vr * VT_PITCH + vc * 16, vg + (size_t)vr * SEQ + vc * 8);
        }
        asm volatile("cp.async.commit_group;" ::: "memory");
    };

    load_tile(0);

    const int rowg1 = q0 + wq * 16 + (lane >> 2);
    const unsigned bOff = (unsigned)(((lane & 7) + ((lane >> 4) * 8)) * QK_PITCH
                                     + ((lane >> 3) & 1) * 16);
    const unsigned vOff = (unsigned)(((lane & 7) + ((lane >> 4) * 8)) * VT_PITCH
                                     + ((lane >> 3) & 1) * 16);

    for (int j = 0; j <= jmax; j++) {
        asm volatile("cp.async.wait_group 0;" ::: "memory");
        __syncthreads();
        if (j < jmax) load_tile(j + 1);

        float sacc[8][4];
#pragma unroll
        for (int nt = 0; nt < 8; nt++)
#pragma unroll
            for (int c = 0; c < 4; c++) sacc[nt][c] = 0.0f;

        const unsigned kbase = sb + ((j & 1) ? OFF_K1 : OFF_K0) + bOff;
#pragma unroll
        for (int kk = 0; kk < 8; kk++) {
            unsigned bf[8][2];
#pragma unroll
            for (int ntp = 0; ntp < 4; ntp++) {
                unsigned r0, r1, r2, r3;
                ldsm_x4(kbase + ntp * (16 * QK_PITCH) + kk * 32, r0, r1, r2, r3);
                bf[2 * ntp][0] = r0;     bf[2 * ntp][1] = r1;
                bf[2 * ntp + 1][0] = r2; bf[2 * ntp + 1][1] = r3;
            }
#pragma unroll
            for (int nt = 0; nt < 8; nt++)
                mma_f16(sacc[nt], qf[kk], bf[nt][0], bf[nt][1]);
        }

        if (j * 64 + 63 > q0 + wq * 16) {
#pragma unroll
            for (int nt = 0; nt < 8; nt++) {
                int colb = j * 64 + nt * 8 + (lane & 3) * 2;
                if (colb     > rowg1)     sacc[nt][0] = -1e30f;
                if (colb + 1 > rowg1)     sacc[nt][1] = -1e30f;
                if (colb     > rowg1 + 8) sacc[nt][2] = -1e30f;
                if (colb + 1 > rowg1 + 8) sacc[nt][3] = -1e30f;
            }
        }

        float tm1 = -1e30f, tm2 = -1e30f;
#pragma unroll
        for (int nt = 0; nt < 8; nt++) {
            tm1 = fmaxf(tm1, fmaxf(sacc[nt][0], sacc[nt][1]));
            tm2 = fmaxf(tm2, fmaxf(sacc[nt][2], sacc[nt][3]));
        }
        tm1 = fmaxf(tm1, __shfl_xor_sync(0xffffffffu, tm1, 1));
        tm1 = fmaxf(tm1, __shfl_xor_sync(0xffffffffu, tm1, 2));
        tm2 = fmaxf(tm2, __shfl_xor_sync(0xffffffffu, tm2, 1));
        tm2 = fmaxf(tm2, __shfl_xor_sync(0xffffffffu, tm2, 2));

        float m1n = fmaxf(m1, tm1), m2n = fmaxf(m2, tm2);
        float corr1 = __expf(m1 - m1n), corr2 = __expf(m2 - m2n);
        m1 = m1n; m2 = m2n;

        float rs1 = 0.0f, rs2 = 0.0f;
#pragma unroll
        for (int nt = 0; nt < 8; nt++) {
            sacc[nt][0] = __expf(sacc[nt][0] - m1n);
            sacc[nt][1] = __expf(sacc[nt][1] - m1n);
            sacc[nt][2] = __expf(sacc[nt][2] - m2n);
            sacc[nt][3] = __expf(sacc[nt][3] - m2n);
            rs1 += sacc[nt][0] + sacc[nt][1];
            rs2 += sacc[nt][2] + sacc[nt][3];
        }
        rs1 += __shfl_xor_sync(0xffffffffu, rs1, 1);
        rs1 += __shfl_xor_sync(0xffffffffu, rs1, 2);
        rs2 += __shfl_xor_sync(0xffffffffu, rs2, 1);
        rs2 += __shfl_xor_sync(0xffffffffu, rs2, 2);
        l1 = l1 * corr1 + rs1;
        l2 = l2 * corr2 + rs2;

#pragma unroll
        for (int nt = 0; nt < 16; nt++) {
            oacc[nt][0] *= corr1; oacc[nt][1] *= corr1;
            oacc[nt][2] *= corr2; oacc[nt][3] *= corr2;
        }

        {
            int pr1 = wq * 16 + (lane >> 2);
            int pc = (lane & 3) * 2;
#pragma unroll
            for (int nt = 0; nt < 8; nt++) {
                *(__half2*)(smem + OFF_P + pr1 * P_PITCH + (nt * 8 + pc) * 2) =
                    __floats2half2_rn(sacc[nt][0], sacc[nt][1]);
                *(__half2*)(smem + OFF_P + (pr1 + 8) * P_PITCH + (nt * 8 + pc) * 2) =
                    __floats2half2_rn(sacc[nt][2], sacc[nt][3]);
            }
        }
        __syncthreads();

        const unsigned vbase = sb + ((j & 1) ? OFF_V1 : OFF_V0) + vOff;
        const unsigned paddr = sb + OFF_P + (wq * 16 + (lane & 15)) * P_PITCH
                             + (lane >> 4) * 16;
#pragma unroll
        for (int kk2 = 0; kk2 < 4; kk2++) {
            unsigned pf[4];
            ldsm_x4(paddr + kk2 * 32, pf[0], pf[1], pf[2], pf[3]);
#pragma unroll
            for (int ntp = 0; ntp < 8; ntp++) {
                unsigned r0, r1, r2, r3;
                ldsm_x4(vbase + ntp * (16 * VT_PITCH) + kk2 * 32, r0, r1, r2, r3);
                mma_f16(oacc[2 * ntp],     pf, r0, r1);
                mma_f16(oacc[2 * ntp + 1], pf, r2, r3);
            }
        }
    }

    float inv1 = 1.0f / l1, inv2 = 1.0f / l2;
    int b = bh >> 4, h = bh & 15;
    int row1 = q0 + wq * 16 + (lane >> 2);
#pragma unroll
    for (int nt = 0; nt < 16; nt++) {
        int d = nt * 8 + (lane & 3) * 2;
        __half* p0 = g_y + (size_t)(b * SEQ + row1) * CDIM + h * HD + d;
        __half* p1 = g_y + (size_t)(b * SEQ + row1 + 8) * CDIM + h * HD + d;
        *(__half2*)p0 = __floats2half2_rn(oacc[nt][0] * inv1, oacc[nt][1] * inv1);
        *(__half2*)p1 = __floats2half2_rn(oacc[nt][2] * inv2, oacc[nt][3] * inv2);
    }
}

// ---------------------------------------------------------------------------
extern "C" void kernel_launch(void* const* d_in, const int* in_sizes, int n_in,
                              void* d_out, int out_size)
{
    (void)in_sizes; (void)n_in; (void)out_size;
    const float* x    = (const float*)d_in[0];
    const float* Wqkv = (const float*)d_in[1];
    const float* Wout = (const float*)d_in[2];
    float* out = (float*)d_out;

    __half *y_p, *xh_p, *w1_p, *w2_p;
    cudaGetSymbolAddress((void**)&y_p,  g_y);
    cudaGetSymbolAddress((void**)&xh_p, g_xh);
    cudaGetSymbolAddress((void**)&w1_p, g_w1);
    cudaGetSymbolAddress((void**)&w2_p, g_w2);

    cudaFuncSetAttribute(gemm_f16mma,
                         cudaFuncAttributeMaxDynamicSharedMemorySize, GEMM_SMEM);
    cudaFuncSetAttribute(gemm_qkv_fused,
                         cudaFuncAttributeMaxDynamicSharedMemorySize, GEMM_SMEM);
    cudaFuncSetAttribute(fattn_kernel,
                         cudaFuncAttributeMaxDynamicSharedMemorySize, ATTN_SMEM);

    // 0) fp32 -> fp16 of x and Wqkv (Wout converted inside the QKV launch)
    tohalf_all_kernel<<<2368, 256>>>(
        (const float4*)x,    (__half2*)xh_p, MTOK * CDIM / 4,
        (const float4*)Wqkv, (__half2*)w1_p, F3 * CDIM / 4);

    // 1) qkv GEMM (fused RoPE/split/scale/V-transpose) + w2-convert slice
    gemm_qkv_fused<<<dim3(F3 / BN, MTOK / BM + 1), 256, GEMM_SMEM>>>(
        xh_p, w1_p, (const float4*)Wout, (__half2*)w2_p);

    // 2) flash attention (fp16 mma, Bc=64, heavy-first) -> y
    fattn_kernel<<<dim3(SEQ / 64, BATCH * NH), 128, ATTN_SMEM>>>();

    // 3) out = y @ Wout^T  (fp32 output)
    gemm_f16mma<<<dim3(CDIM / BN, MTOK / BM), 256, GEMM_SMEM>>>(y_p, w2_p, out, CDIM, CDIM);
}